// round 10
// baseline (speedup 1.0000x reference)
#include <cuda_runtime.h>
#include <cuda_fp16.h>
#include <mma.h>
#include <math.h>
#include <stdint.h>

using namespace nvcuda;

#define NA 50000
#define NE 800000
#define ND 64
#define FULL 192
#define NOUT 128          // cols 0..63 = core, 64..127 = filter
#define ET 128            // edges per tile
#define NTILES (NE / ET)  // 6250
#define GRID0 148
#define THREADS0 512
#define WLDH 136          // W smem leading dim (halves)
#define ZLDH 200          // z tile leading dim (halves): 192 + 8 pad
#define SLD 20            // scratch leading dim (floats)
#define BN_EPS 1e-5f

// dyn smem: W(192x136h) + 2 z(128x200h) + scratch(16 warps x 16x20 f32) + idx
#define SMEM0_BYTES (FULL*WLDH*2 + 2*ET*ZLDH*2 + 16*16*SLD*4 + 4*ET*4)

__device__ __align__(16) __half g_Wt_h[FULL * NOUT];        // Wt[k][o]
__device__ __align__(16) __half g_atom_h[NA * ND];
__device__ __align__(16) __half g_edge_h[(size_t)NE * ND];
__device__ float g_sum[NOUT];
__device__ float g_sumsq[NOUT];
__device__ float g_scale[NOUT];
__device__ float g_shift[NOUT];
__device__ int   g_idx64;
__device__ __align__(16) __half g_pre_h[(size_t)NE * NOUT]; // 204.8 MB

__device__ __forceinline__ void cp_async16(void* sdst, const void* gsrc) {
    unsigned saddr = (unsigned)__cvta_generic_to_shared(sdst);
    asm volatile("cp.async.ca.shared.global [%0], [%1], 16;"
                 :: "r"(saddr), "l"(gsrc) : "memory");
}

// ---------------------------------------------------------------------------
// prep: out = atom copy; atom/edge/W -> half; zero stats; idx dtype sniff
// ---------------------------------------------------------------------------
__global__ void prep_kernel(const float* __restrict__ atom,
                            const float* __restrict__ edgef,
                            const float* __restrict__ Wf,
                            const float* __restrict__ Wc,
                            const int* __restrict__ eidx_i32,
                            float* __restrict__ out) {
    int tid = blockIdx.x * blockDim.x + threadIdx.x;
    int stride = gridDim.x * blockDim.x;

    for (int i = tid; i < (NA * ND) / 4; i += stride) {
        float4 v = reinterpret_cast<const float4*>(atom)[i];
        reinterpret_cast<float4*>(out)[i] = v;
        __half2* h = reinterpret_cast<__half2*>(g_atom_h) + 2 * i;
        h[0] = __floats2half2_rn(v.x, v.y);
        h[1] = __floats2half2_rn(v.z, v.w);
    }
    for (long long i = tid; i < ((long long)NE * ND) / 4; i += stride) {
        float4 v = reinterpret_cast<const float4*>(edgef)[i];
        __half2* h = reinterpret_cast<__half2*>(g_edge_h) + 2 * i;
        h[0] = __floats2half2_rn(v.x, v.y);
        h[1] = __floats2half2_rn(v.z, v.w);
    }
    for (int i = tid; i < FULL * NOUT; i += stride) {
        int k = i / NOUT, o = i % NOUT;
        float w = (o < ND) ? Wc[o * FULL + k] : Wf[(o - ND) * FULL + k];
        g_Wt_h[i] = __float2half_rn(w);   // bias cancels inside batchnorm
    }
    if (tid < NOUT) { g_sum[tid] = 0.f; g_sumsq[tid] = 0.f; }
    if (tid == 0) {
        int any = 0;
        for (int k = 0; k < 512; k++) any |= eidx_i32[2 * k + 1];
        g_idx64 = (any == 0) ? 1 : 0;   // int64 => zero high words
    }
}

// ---------------------------------------------------------------------------
__global__ void finalize_kernel(const float* __restrict__ gc,
                                const float* __restrict__ bc,
                                const float* __restrict__ gf,
                                const float* __restrict__ bf) {
    int c = threadIdx.x;
    if (c < NOUT) {
        float mean = g_sum[c] * (1.f / (float)NE);
        float var  = g_sumsq[c] * (1.f / (float)NE) - mean * mean;
        float inv  = rsqrtf(var + BN_EPS);
        float gamma = (c < ND) ? gc[c] : gf[c - ND];
        float beta  = (c < ND) ? bc[c] : bf[c - ND];
        g_scale[c] = inv * gamma;
        g_shift[c] = beta - mean * inv * gamma;
    }
}

// ---------------------------------------------------------------------------
// PASS 0: persistent fp16 GEMM, 148 x 512. W resident in smem. Full-width
// 128x192 z tiles, double-buffered: gather(t+1) is in flight across the
// whole MMA(t)+epilogue(t). Pre-activations converted to half via per-warp
// smem scratch and streamed to g_pre_h; stats from the rounded halves.
// ---------------------------------------------------------------------------
__global__ __launch_bounds__(THREADS0, 1)
void pass0_kernel(const void* __restrict__ eidx) {
    extern __shared__ __align__(16) unsigned char smraw[];
    __half* sW  = reinterpret_cast<__half*>(smraw);           // 192*136
    __half* zb[2];
    zb[0] = sW + FULL * WLDH;                                 // 128*200 each
    zb[1] = zb[0] + ET * ZLDH;
    float* scratch = reinterpret_cast<float*>(zb[1] + ET * ZLDH); // 16*320
    int* sSrc = reinterpret_cast<int*>(scratch + 16 * 16 * SLD);  // [2][ET]
    int* sDst = sSrc + 2 * ET;

    const int tid  = threadIdx.x;
    const int w    = tid >> 5;
    const int lane = tid & 31;
    const int bid  = blockIdx.x;
    const int nt   = (NTILES - bid + GRID0 - 1) / GRID0;      // tiles bid+t*148
    const bool i64 = (g_idx64 != 0);

    auto stageIdx = [&](int t) {
        if (tid < ET && t < nt) {
            int slot = t & 1;
            long long e = ((long long)bid + (long long)t * GRID0) * ET + tid;
            if (i64) {
                const long long* p = reinterpret_cast<const long long*>(eidx);
                sSrc[slot * ET + tid] = (int)p[2 * e];
                sDst[slot * ET + tid] = (int)p[2 * e + 1];
            } else {
                const int* p = reinterpret_cast<const int*>(eidx);
                sSrc[slot * ET + tid] = p[2 * e];
                sDst[slot * ET + tid] = p[2 * e + 1];
            }
        }
    };
    // gather full 192-wide z rows for tile t into zb[t&1]; always commits
    auto gather = [&](int t) {
        if (t < nt) {
            int slot = t & 1;
            long long e0 = ((long long)bid + (long long)t * GRID0) * ET;
            __half* zbuf = zb[slot];
            for (int i = tid; i < ET * 24; i += THREADS0) {
                int e = i / 24, seg = i % 24;     // 24 x 8-half chunks
                const __half* g;
                if (seg < 8)       g = g_atom_h + (long long)sDst[slot*ET + e] * ND + seg * 8;
                else if (seg < 16) g = g_atom_h + (long long)sSrc[slot*ET + e] * ND + (seg - 8) * 8;
                else               g = g_edge_h + (e0 + e) * ND + (seg - 16) * 8;
                cp_async16(zbuf + e * ZLDH + seg * 8, g);
            }
        }
        asm volatile("cp.async.commit_group;" ::: "memory");
    };

    // ---- prologue: idx0, W copy + gather(0) in group 0, idx1 ----
    stageIdx(0);
    __syncthreads();
    for (int i = tid; i < FULL * 16; i += THREADS0) {
        int k = i >> 4, q = i & 15;
        cp_async16(sW + k * WLDH + q * 8, g_Wt_h + k * NOUT + q * 8);
    }
    gather(0);
    stageIdx(1);

    const int m0 = (w & 3) * 32;
    const int n0 = (w >> 2) * 32;
    const int scol = tid & 127;
    const int sgrp = tid >> 7;
    float s_acc = 0.f, q_acc = 0.f;
    float* myscr = scratch + w * 16 * SLD;

    wmma::fragment<wmma::matrix_a, 16, 16, 16, __half, wmma::row_major> a0, a1;
    wmma::fragment<wmma::matrix_b, 16, 16, 16, __half, wmma::row_major> b0, b1;
    wmma::fragment<wmma::accumulator, 16, 16, 16, float> acc[2][2];

    for (int t = 0; t < nt; t++) {
        long long e0 = ((long long)bid + (long long)t * GRID0) * ET;

        asm volatile("cp.async.wait_group 0;" ::: "memory");
        __syncthreads();                 // z_t (and W at t=0) visible; idx staged
        gather(t + 1);                   // in flight across MMA + epilogue

        const __half* z = zb[t & 1];
#pragma unroll
        for (int m = 0; m < 2; m++)
#pragma unroll
            for (int n = 0; n < 2; n++) wmma::fill_fragment(acc[m][n], 0.f);

#pragma unroll
        for (int k = 0; k < FULL / 16; k++) {
            wmma::load_matrix_sync(a0, z + (m0)      * ZLDH + k * 16, ZLDH);
            wmma::load_matrix_sync(a1, z + (m0 + 16) * ZLDH + k * 16, ZLDH);
            wmma::load_matrix_sync(b0, sW + (k * 16) * WLDH + n0,      WLDH);
            wmma::load_matrix_sync(b1, sW + (k * 16) * WLDH + n0 + 16, WLDH);
            wmma::mma_sync(acc[0][0], a0, b0, acc[0][0]);
            wmma::mma_sync(acc[0][1], a0, b1, acc[0][1]);
            wmma::mma_sync(acc[1][0], a1, b0, acc[1][0]);
            wmma::mma_sync(acc[1][1], a1, b1, acc[1][1]);
        }

        // ---- epilogue: f32 acc -> half via per-warp scratch -> g_pre_h ----
        const int r  = lane >> 1;
        const int cb = (lane & 1) * 8;
#pragma unroll
        for (int m = 0; m < 2; m++)
#pragma unroll
            for (int n = 0; n < 2; n++) {
                wmma::store_matrix_sync(myscr, acc[m][n], SLD, wmma::mem_row_major);
                __syncwarp();
                const float* s = myscr + r * SLD + cb;
                __half2 h[4];
                h[0] = __floats2half2_rn(s[0], s[1]);
                h[1] = __floats2half2_rn(s[2], s[3]);
                h[2] = __floats2half2_rn(s[4], s[5]);
                h[3] = __floats2half2_rn(s[6], s[7]);
                *reinterpret_cast<uint4*>(
                    g_pre_h + (size_t)(e0 + m0 + m * 16 + r) * NOUT + n0 + n * 16 + cb)
                    = *reinterpret_cast<uint4*>(h);
                __syncwarp();
            }
        __syncthreads();                 // g_pre_h writes visible; zb[t&1] free

        // ---- stats from rounded halves (L2-resident) ----
        const __half* baseh = g_pre_h + (size_t)(e0 + sgrp * 32) * NOUT + scol;
#pragma unroll 4
        for (int e = 0; e < 32; e++) {
            float v = __half2float(baseh[(size_t)e * NOUT]);
            s_acc += v; q_acc += v * v;
        }

        stageIdx(t + 2);                 // slot t&1 (read by gather(t+2))
    }

    atomicAdd(&g_sum[scol],   s_acc);
    atomicAdd(&g_sumsq[scol], q_acc);
}

// ---------------------------------------------------------------------------
// PASS 1: streaming epilogue over half pre-acts: BN + softplus*sigmoid +
// red.v4 scatter to out[dst].
// ---------------------------------------------------------------------------
__global__ __launch_bounds__(256)
void pass1_kernel(const void* __restrict__ eidx,
                  float* __restrict__ out) {
    __shared__ float sBN[2 * NOUT];
    const int tid = threadIdx.x;
    if (tid < NOUT) sBN[tid] = g_scale[tid];
    else            sBN[128 + (tid - 128)] = g_shift[tid - 128];
    __syncthreads();

    long long i = (long long)blockIdx.x * 256 + tid;   // NE*16 total
    int e = (int)(i >> 4), q = (int)(i & 15);

    int dst;
    if (g_idx64) dst = (int)reinterpret_cast<const long long*>(eidx)[2ll * e + 1];
    else         dst = reinterpret_cast<const int*>(eidx)[2 * e + 1];

    const __half* row = g_pre_h + (size_t)e * NOUT;
    __half2 hc[2], hf[2];
    *reinterpret_cast<uint2*>(hc) = *reinterpret_cast<const uint2*>(row + q * 4);
    *reinterpret_cast<uint2*>(hf) = *reinterpret_cast<const uint2*>(row + 64 + q * 4);
    float2 c01 = __half22float2(hc[0]), c23 = __half22float2(hc[1]);
    float2 f01 = __half22float2(hf[0]), f23 = __half22float2(hf[1]);
    float xc[4] = {c01.x, c01.y, c23.x, c23.y};
    float xf[4] = {f01.x, f01.y, f23.x, f23.y};

    float m[4];
#pragma unroll
    for (int u = 0; u < 4; u++) {
        int c = q * 4 + u;
        float vc = xc[u] * sBN[c]      + sBN[NOUT + c];
        float vf = xf[u] * sBN[64 + c] + sBN[NOUT + 64 + c];
        float sp = fmaxf(vc, 0.f) + log1pf(__expf(-fabsf(vc)));   // softplus
        float sg = __fdividef(1.f, 1.f + __expf(-vf));            // sigmoid
        m[u] = sp * sg;
    }
    float* ptr = out + (long long)dst * ND + q * 4;
    asm volatile("red.global.add.v4.f32 [%0], {%1,%2,%3,%4};"
                 :: "l"(ptr), "f"(m[0]), "f"(m[1]), "f"(m[2]), "f"(m[3])
                 : "memory");
}

// ---------------------------------------------------------------------------
extern "C" void kernel_launch(void* const* d_in, const int* in_sizes, int n_in,
                              void* d_out, int out_size) {
    const float* atom  = (const float*)d_in[0];
    const float* edgef = (const float*)d_in[1];
    const float* Wf    = (const float*)d_in[2];
    const float* gf    = (const float*)d_in[4];
    const float* bf    = (const float*)d_in[5];
    const float* Wc    = (const float*)d_in[6];
    const float* gc    = (const float*)d_in[8];
    const float* bc    = (const float*)d_in[9];
    const void*  eidx  = d_in[10];
    float* out = (float*)d_out;

    cudaFuncSetAttribute(pass0_kernel,
                         cudaFuncAttributeMaxDynamicSharedMemorySize,
                         SMEM0_BYTES);

    prep_kernel<<<2048, 256>>>(atom, edgef, Wf, Wc, (const int*)eidx, out);
    pass0_kernel<<<GRID0, THREADS0, SMEM0_BYTES>>>(eidx);
    finalize_kernel<<<1, 128>>>(gc, bc, gf, bf);
    pass1_kernel<<<(NE * 16) / 256, 256>>>(eidx, out);
}

// round 11
// speedup vs baseline: 1.2776x; 1.2776x over previous
#include <cuda_runtime.h>
#include <cuda_fp16.h>
#include <mma.h>
#include <math.h>
#include <stdint.h>

using namespace nvcuda;

#define NA 50000
#define NE 800000
#define ND 64
#define FULL 192
#define NOUT 128          // cols 0..63 = core, 64..127 = filter
#define ET 256            // edges per tile
#define NTILES (NE / ET)  // 3125
#define GRID0 148
#define THREADS0 512
#define WLDH 136          // W smem leading dim (halves)
#define ZLDH 72           // z chunk leading dim (halves): 64 + 8 pad
#define BN_EPS 1e-5f

// dyn smem: W (192x136 half) + 2 z-chunks (256x72 half) + 2x(src,dst)[256]
#define SMEM0_BYTES ((FULL * WLDH + 2 * ET * ZLDH) * 2 + 4 * ET * 4)

__device__ __align__(16) __half g_Wt_h[FULL * NOUT];   // Wt[k][o] half
__device__ __align__(16) __half g_atom_h[NA * ND];
__device__ __align__(16) __half g_edge_h[(size_t)NE * ND];
__device__ float g_sum[NOUT];
__device__ float g_sumsq[NOUT];
__device__ float g_scale[NOUT];
__device__ float g_shift[NOUT];
__device__ int   g_idx64;
__device__ float g_pre[(size_t)NE * NOUT];             // 409.6 MB scratch

__device__ __forceinline__ void cp_async16(void* sdst, const void* gsrc) {
    unsigned saddr = (unsigned)__cvta_generic_to_shared(sdst);
    asm volatile("cp.async.ca.shared.global [%0], [%1], 16;"
                 :: "r"(saddr), "l"(gsrc) : "memory");
}

// ---------------------------------------------------------------------------
// prep: out = atom copy; atom/edge/W -> half; zero stats; idx dtype sniff
// ---------------------------------------------------------------------------
__global__ void prep_kernel(const float* __restrict__ atom,
                            const float* __restrict__ edgef,
                            const float* __restrict__ Wf,
                            const float* __restrict__ Wc,
                            const int* __restrict__ eidx_i32,
                            float* __restrict__ out) {
    int tid = blockIdx.x * blockDim.x + threadIdx.x;
    int stride = gridDim.x * blockDim.x;

    for (int i = tid; i < (NA * ND) / 4; i += stride) {
        float4 v = reinterpret_cast<const float4*>(atom)[i];
        reinterpret_cast<float4*>(out)[i] = v;
        __half2* h = reinterpret_cast<__half2*>(g_atom_h) + 2 * i;
        h[0] = __floats2half2_rn(v.x, v.y);
        h[1] = __floats2half2_rn(v.z, v.w);
    }
    for (long long i = tid; i < ((long long)NE * ND) / 4; i += stride) {
        float4 v = reinterpret_cast<const float4*>(edgef)[i];
        __half2* h = reinterpret_cast<__half2*>(g_edge_h) + 2 * i;
        h[0] = __floats2half2_rn(v.x, v.y);
        h[1] = __floats2half2_rn(v.z, v.w);
    }
    for (int i = tid; i < FULL * NOUT; i += stride) {
        int k = i / NOUT, o = i % NOUT;
        float w = (o < ND) ? Wc[o * FULL + k] : Wf[(o - ND) * FULL + k];
        g_Wt_h[i] = __float2half_rn(w);   // bias cancels inside batchnorm
    }
    if (tid < NOUT) { g_sum[tid] = 0.f; g_sumsq[tid] = 0.f; }
    if (tid == 0) {
        int any = 0;
        for (int k = 0; k < 512; k++) any |= eidx_i32[2 * k + 1];
        g_idx64 = (any == 0) ? 1 : 0;   // int64 => zero high words
    }
}

// ---------------------------------------------------------------------------
__global__ void finalize_kernel(const float* __restrict__ gc,
                                const float* __restrict__ bc,
                                const float* __restrict__ gf,
                                const float* __restrict__ bf) {
    int c = threadIdx.x;
    if (c < NOUT) {
        float mean = g_sum[c] * (1.f / (float)NE);
        float var  = g_sumsq[c] * (1.f / (float)NE) - mean * mean;
        float inv  = rsqrtf(var + BN_EPS);
        float gamma = (c < ND) ? gc[c] : gf[c - ND];
        float beta  = (c < ND) ? bc[c] : bf[c - ND];
        g_scale[c] = inv * gamma;
        g_shift[c] = beta - mean * inv * gamma;
    }
}

// ---------------------------------------------------------------------------
// PASS 0: persistent fp16 GEMM, 148 x 512 threads. W resident in smem.
// 256-edge tiles, K in 3 chunks of 64 halves (dst/src/edge), double-buffered
// cp.async (wait_group 1). Warp grid 4m x 4n groups: warp = 64 edges (4 m
// fragments) x 32 cols (2 n fragments) -> 6 loads feed 8 MMAs per k-step.
// Streams pre-activations to g_pre; column stats in regs -> atomics at end.
// ---------------------------------------------------------------------------
__global__ __launch_bounds__(THREADS0, 1)
void pass0_kernel(const void* __restrict__ eidx) {
    extern __shared__ __align__(16) unsigned char smraw[];
    __half* sW = reinterpret_cast<__half*>(smraw);        // 192*136 halves
    __half* zb[2];
    zb[0] = sW + FULL * WLDH;                             // 256*72 halves each
    zb[1] = zb[0] + ET * ZLDH;
    int* sSrc = reinterpret_cast<int*>(zb[1] + ET * ZLDH);   // [2][ET]
    int* sDst = sSrc + 2 * ET;

    const int tid = threadIdx.x;
    const int bid = blockIdx.x;
    const int nt  = (NTILES - bid + GRID0 - 1) / GRID0;   // tiles bid + t*148
    const bool i64 = (g_idx64 != 0);

    auto stageIdx = [&](int t) {
        if (tid < ET && t < nt) {
            int slot = t & 1;
            long long e = ((long long)bid + (long long)t * GRID0) * ET + tid;
            if (i64) {
                const long long* p = reinterpret_cast<const long long*>(eidx);
                sSrc[slot * ET + tid] = (int)p[2 * e];
                sDst[slot * ET + tid] = (int)p[2 * e + 1];
            } else {
                const int* p = reinterpret_cast<const int*>(eidx);
                sSrc[slot * ET + tid] = p[2 * e];
                sDst[slot * ET + tid] = p[2 * e + 1];
            }
        }
    };
    // gather K-chunk c (tile t = c/3, phase p = c%3) into zb[c&1]; always commits
    auto gather = [&](int c) {
        int t = c / 3, p = c - 3 * t;
        if (t < nt) {
            int islot = t & 1;
            long long e0 = ((long long)bid + (long long)t * GRID0) * ET;
            __half* zbuf = zb[c & 1];
            // 8 x 16B (= 64 halves) per edge row
            for (int i = tid; i < ET * 8; i += THREADS0) {
                int e = i >> 3, q = i & 7;
                const __half* g;
                if (p == 0)      g = g_atom_h + (long long)sDst[islot*ET + e] * ND + q * 8;
                else if (p == 1) g = g_atom_h + (long long)sSrc[islot*ET + e] * ND + q * 8;
                else             g = g_edge_h + (e0 + e) * ND + q * 8;
                cp_async16(zbuf + e * ZLDH + q * 8, g);
            }
        }
        asm volatile("cp.async.commit_group;" ::: "memory");
    };

    // ---- prologue: W copy + chunk0 (group 0), chunk1 (group 1) ----
    stageIdx(0);
    __syncthreads();
    for (int i = tid; i < FULL * 16; i += THREADS0) {
        int k = i >> 4, q = i & 15;
        cp_async16(sW + k * WLDH + q * 8, g_Wt_h + k * NOUT + q * 8);
    }
    gather(0);          // W + chunk0 committed together
    gather(1);

    const int w  = tid >> 5;
    const int m0 = (w & 3) * 64;       // 4 m-fragments (64 edges)
    const int n0 = (w >> 2) * 32;      // 2 n-fragments (32 cols)
    const int scol = tid & 127;        // stats column
    const int sgrp = tid >> 7;         // edge quarter (0..3), 64 edges each
    float s_acc = 0.f, q_acc = 0.f;

    wmma::fragment<wmma::matrix_a, 16, 16, 16, __half, wmma::row_major> a[4];
    wmma::fragment<wmma::matrix_b, 16, 16, 16, __half, wmma::row_major> b0, b1;
    wmma::fragment<wmma::accumulator, 16, 16, 16, float> acc[4][2];

    for (int t = 0; t < nt; t++) {
        long long e0 = ((long long)bid + (long long)t * GRID0) * ET;

#pragma unroll
        for (int p = 0; p < 3; p++) {
            const int c = 3 * t + p;
            asm volatile("cp.async.wait_group 1;" ::: "memory");
            __syncthreads();             // chunk c visible; zb[c&1] owned

            if (p == 0) {
                stageIdx(t + 1);         // idx for next tile (used at c+3)
#pragma unroll
                for (int m = 0; m < 4; m++)
#pragma unroll
                    for (int n = 0; n < 2; n++) wmma::fill_fragment(acc[m][n], 0.f);
            }

            const __half* z = zb[c & 1];
#pragma unroll
            for (int k = 0; k < 4; k++) {
#pragma unroll
                for (int m = 0; m < 4; m++)
                    wmma::load_matrix_sync(a[m], z + (m0 + m * 16) * ZLDH + k * 16, ZLDH);
                wmma::load_matrix_sync(b0, sW + (p * 64 + k * 16) * WLDH + n0,      WLDH);
                wmma::load_matrix_sync(b1, sW + (p * 64 + k * 16) * WLDH + n0 + 16, WLDH);
#pragma unroll
                for (int m = 0; m < 4; m++) {
                    wmma::mma_sync(acc[m][0], a[m], b0, acc[m][0]);
                    wmma::mma_sync(acc[m][1], a[m], b1, acc[m][1]);
                }
            }
            __syncthreads();             // all warps done with zb[c&1]
            gather(c + 2);               // refill freed buffer (in flight)
        }

        // ---- tile epilogue: stream C to g_pre, fold stats from L2 ----
#pragma unroll
        for (int m = 0; m < 4; m++)
#pragma unroll
            for (int n = 0; n < 2; n++)
                wmma::store_matrix_sync(
                    g_pre + (size_t)(e0 + m0 + m * 16) * NOUT + n0 + n * 16,
                    acc[m][n], NOUT, wmma::mem_row_major);
        __syncthreads();                 // C visible block-wide

        const float* base = g_pre + (size_t)(e0 + sgrp * 64) * NOUT + scol;
#pragma unroll 8
        for (int e = 0; e < 64; e++) {
            float v = base[(size_t)e * NOUT];
            s_acc += v; q_acc += v * v;
        }
    }

    atomicAdd(&g_sum[scol],   s_acc);
    atomicAdd(&g_sumsq[scol], q_acc);
}

// ---------------------------------------------------------------------------
// PASS 1: streaming epilogue: BN fold + softplus*sigmoid + red.v4 scatter.
// ---------------------------------------------------------------------------
__global__ __launch_bounds__(256)
void pass1_kernel(const void* __restrict__ eidx,
                  float* __restrict__ out) {
    __shared__ float sBN[2 * NOUT];
    const int tid = threadIdx.x;
    if (tid < NOUT) sBN[tid] = g_scale[tid];
    else            sBN[128 + (tid - 128)] = g_shift[tid - 128];
    __syncthreads();

    long long i = (long long)blockIdx.x * 256 + tid;   // NE*16 total
    int e = (int)(i >> 4), q = (int)(i & 15);

    int dst;
    if (g_idx64) dst = (int)reinterpret_cast<const long long*>(eidx)[2ll * e + 1];
    else         dst = reinterpret_cast<const int*>(eidx)[2 * e + 1];

    const float* row = g_pre + (size_t)e * NOUT;
    float4 xc4 = *reinterpret_cast<const float4*>(row + q * 4);
    float4 xf4 = *reinterpret_cast<const float4*>(row + 64 + q * 4);
    float xc[4] = {xc4.x, xc4.y, xc4.z, xc4.w};
    float xf[4] = {xf4.x, xf4.y, xf4.z, xf4.w};

    float m[4];
#pragma unroll
    for (int u = 0; u < 4; u++) {
        int c = q * 4 + u;
        float vc = xc[u] * sBN[c]      + sBN[NOUT + c];
        float vf = xf[u] * sBN[64 + c] + sBN[NOUT + 64 + c];
        // softplus via MUFU: max(x,0) + log(1 + exp(-|x|))
        float sp = fmaxf(vc, 0.f) + __logf(1.f + __expf(-fabsf(vc)));
        float sg = __fdividef(1.f, 1.f + __expf(-vf));            // sigmoid
        m[u] = sp * sg;
    }
    float* ptr = out + (long long)dst * ND + q * 4;
    asm volatile("red.global.add.v4.f32 [%0], {%1,%2,%3,%4};"
                 :: "l"(ptr), "f"(m[0]), "f"(m[1]), "f"(m[2]), "f"(m[3])
                 : "memory");
}

// ---------------------------------------------------------------------------
extern "C" void kernel_launch(void* const* d_in, const int* in_sizes, int n_in,
                              void* d_out, int out_size) {
    const float* atom  = (const float*)d_in[0];
    const float* edgef = (const float*)d_in[1];
    const float* Wf    = (const float*)d_in[2];
    const float* gf    = (const float*)d_in[4];
    const float* bf    = (const float*)d_in[5];
    const float* Wc    = (const float*)d_in[6];
    const float* gc    = (const float*)d_in[8];
    const float* bc    = (const float*)d_in[9];
    const void*  eidx  = d_in[10];
    float* out = (float*)d_out;

    cudaFuncSetAttribute(pass0_kernel,
                         cudaFuncAttributeMaxDynamicSharedMemorySize,
                         SMEM0_BYTES);

    prep_kernel<<<2048, 256>>>(atom, edgef, Wf, Wc, (const int*)eidx, out);
    pass0_kernel<<<GRID0, THREADS0, SMEM0_BYTES>>>(eidx);
    finalize_kernel<<<1, 128>>>(gc, bc, gf, bf);
    pass1_kernel<<<(NE * 16) / 256, 256>>>(eidx, out);
}

// round 12
// speedup vs baseline: 1.3325x; 1.0430x over previous
#include <cuda_runtime.h>
#include <cuda_fp16.h>
#include <mma.h>
#include <math.h>
#include <stdint.h>

using namespace nvcuda;

#define NA 50000
#define NE 800000
#define ND 64
#define FULL 192
#define NOUT 128          // cols 0..63 = core, 64..127 = filter
#define ET 128            // edges per tile
#define NTILES (NE / ET)  // 6250
#define GRID0 296         // 2 persistent CTAs per SM
#define THREADS0 256
#define WLDH 136          // W smem leading dim (halves)
#define ZLDH 72           // z chunk leading dim (halves): 64 + 8 pad
#define BN_EPS 1e-5f

// dyn smem: W (192x136 half) + 2 z-chunks (128x72 half) + 2x(src,dst)[128]
#define SMEM0_BYTES ((FULL * WLDH + 2 * ET * ZLDH) * 2 + 4 * ET * 4)

__device__ __align__(16) __half g_Wt_h[FULL * NOUT];   // Wt[k][o] half
__device__ __align__(16) __half g_atom_h[NA * ND];
__device__ __align__(16) __half g_edge_h[(size_t)NE * ND];
__device__ float g_sum[NOUT];
__device__ float g_sumsq[NOUT];
__device__ float g_scale[NOUT];
__device__ float g_shift[NOUT];
__device__ int   g_idx64;
__device__ float g_pre[(size_t)NE * NOUT];             // 409.6 MB scratch

__device__ __forceinline__ void cp_async16(void* sdst, const void* gsrc) {
    unsigned saddr = (unsigned)__cvta_generic_to_shared(sdst);
    asm volatile("cp.async.ca.shared.global [%0], [%1], 16;"
                 :: "r"(saddr), "l"(gsrc) : "memory");
}

// ---------------------------------------------------------------------------
// prep: out = atom copy; atom/edge/W -> half; zero stats; idx dtype sniff
// ---------------------------------------------------------------------------
__global__ void prep_kernel(const float* __restrict__ atom,
                            const float* __restrict__ edgef,
                            const float* __restrict__ Wf,
                            const float* __restrict__ Wc,
                            const int* __restrict__ eidx_i32,
                            float* __restrict__ out) {
    int tid = blockIdx.x * blockDim.x + threadIdx.x;
    int stride = gridDim.x * blockDim.x;

    for (int i = tid; i < (NA * ND) / 4; i += stride) {
        float4 v = reinterpret_cast<const float4*>(atom)[i];
        reinterpret_cast<float4*>(out)[i] = v;
        __half2* h = reinterpret_cast<__half2*>(g_atom_h) + 2 * i;
        h[0] = __floats2half2_rn(v.x, v.y);
        h[1] = __floats2half2_rn(v.z, v.w);
    }
    for (long long i = tid; i < ((long long)NE * ND) / 4; i += stride) {
        float4 v = reinterpret_cast<const float4*>(edgef)[i];
        __half2* h = reinterpret_cast<__half2*>(g_edge_h) + 2 * i;
        h[0] = __floats2half2_rn(v.x, v.y);
        h[1] = __floats2half2_rn(v.z, v.w);
    }
    for (int i = tid; i < FULL * NOUT; i += stride) {
        int k = i / NOUT, o = i % NOUT;
        float w = (o < ND) ? Wc[o * FULL + k] : Wf[(o - ND) * FULL + k];
        g_Wt_h[i] = __float2half_rn(w);   // bias cancels inside batchnorm
    }
    if (tid < NOUT) { g_sum[tid] = 0.f; g_sumsq[tid] = 0.f; }
    if (tid == 0) {
        int any = 0;
        for (int k = 0; k < 512; k++) any |= eidx_i32[2 * k + 1];
        g_idx64 = (any == 0) ? 1 : 0;   // int64 => zero high words
    }
}

// ---------------------------------------------------------------------------
__global__ void finalize_kernel(const float* __restrict__ gc,
                                const float* __restrict__ bc,
                                const float* __restrict__ gf,
                                const float* __restrict__ bf) {
    int c = threadIdx.x;
    if (c < NOUT) {
        float mean = g_sum[c] * (1.f / (float)NE);
        float var  = g_sumsq[c] * (1.f / (float)NE) - mean * mean;
        float inv  = rsqrtf(var + BN_EPS);
        float gamma = (c < ND) ? gc[c] : gf[c - ND];
        float beta  = (c < ND) ? bc[c] : bf[c - ND];
        g_scale[c] = inv * gamma;
        g_shift[c] = beta - mean * inv * gamma;
    }
}

// ---------------------------------------------------------------------------
// PASS 0: persistent fp16 GEMM, 296 blocks x 256 threads (2 CTAs/SM so one
// block's MMA covers the other's barriers/epilogue). W resident in smem.
// 128-edge tiles, K in 3 chunks of 64 halves (dst/src/edge), double-buffered
// cp.async (wait_group 1). Warp = 64 edges (4 m frags) x 32 cols (2 n frags).
// Streams pre-activations to g_pre; column stats in regs -> atomics at end.
// ---------------------------------------------------------------------------
__global__ __launch_bounds__(THREADS0, 2)
void pass0_kernel(const void* __restrict__ eidx) {
    extern __shared__ __align__(16) unsigned char smraw[];
    __half* sW = reinterpret_cast<__half*>(smraw);        // 192*136 halves
    __half* zb[2];
    zb[0] = sW + FULL * WLDH;                             // 128*72 halves each
    zb[1] = zb[0] + ET * ZLDH;
    int* sSrc = reinterpret_cast<int*>(zb[1] + ET * ZLDH);   // [2][ET]
    int* sDst = sSrc + 2 * ET;

    const int tid = threadIdx.x;
    const int bid = blockIdx.x;
    const int nt  = (NTILES - bid + GRID0 - 1) / GRID0;   // tiles bid + t*296
    const bool i64 = (g_idx64 != 0);

    auto stageIdx = [&](int t) {
        if (tid < ET && t < nt) {
            int slot = t & 1;
            long long e = ((long long)bid + (long long)t * GRID0) * ET + tid;
            if (i64) {
                const long long* p = reinterpret_cast<const long long*>(eidx);
                sSrc[slot * ET + tid] = (int)p[2 * e];
                sDst[slot * ET + tid] = (int)p[2 * e + 1];
            } else {
                const int* p = reinterpret_cast<const int*>(eidx);
                sSrc[slot * ET + tid] = p[2 * e];
                sDst[slot * ET + tid] = p[2 * e + 1];
            }
        }
    };
    // gather K-chunk c (tile t = c/3, phase p = c%3) into zb[c&1]; always commits
    auto gather = [&](int c) {
        int t = c / 3, p = c - 3 * t;
        if (t < nt) {
            int islot = t & 1;
            long long e0 = ((long long)bid + (long long)t * GRID0) * ET;
            __half* zbuf = zb[c & 1];
            // 8 x 16B (= 64 halves) per edge row
            for (int i = tid; i < ET * 8; i += THREADS0) {
                int e = i >> 3, q = i & 7;
                const __half* g;
                if (p == 0)      g = g_atom_h + (long long)sDst[islot*ET + e] * ND + q * 8;
                else if (p == 1) g = g_atom_h + (long long)sSrc[islot*ET + e] * ND + q * 8;
                else             g = g_edge_h + (e0 + e) * ND + q * 8;
                cp_async16(zbuf + e * ZLDH + q * 8, g);
            }
        }
        asm volatile("cp.async.commit_group;" ::: "memory");
    };

    // ---- prologue: W copy + chunk0 (group 0), chunk1 (group 1) ----
    stageIdx(0);
    __syncthreads();
    for (int i = tid; i < FULL * 16; i += THREADS0) {
        int k = i >> 4, q = i & 15;
        cp_async16(sW + k * WLDH + q * 8, g_Wt_h + k * NOUT + q * 8);
    }
    gather(0);          // W + chunk0 committed together
    gather(1);

    const int w  = tid >> 5;
    const int m0 = (w & 1) * 64;       // 4 m-fragments (64 edges)
    const int n0 = (w >> 1) * 32;      // 2 n-fragments (32 cols)
    const int scol = tid & 127;        // stats column
    const int sgrp = tid >> 7;         // edge half (0/1), 64 edges each
    float s_acc = 0.f, q_acc = 0.f;

    wmma::fragment<wmma::matrix_a, 16, 16, 16, __half, wmma::row_major> a[4];
    wmma::fragment<wmma::matrix_b, 16, 16, 16, __half, wmma::row_major> b0, b1;
    wmma::fragment<wmma::accumulator, 16, 16, 16, float> acc[4][2];

    for (int t = 0; t < nt; t++) {
        long long e0 = ((long long)bid + (long long)t * GRID0) * ET;

#pragma unroll
        for (int p = 0; p < 3; p++) {
            const int c = 3 * t + p;
            asm volatile("cp.async.wait_group 1;" ::: "memory");
            __syncthreads();             // chunk c visible; zb[c&1] owned

            if (p == 0) {
                stageIdx(t + 1);         // idx for next tile (used at c+3)
#pragma unroll
                for (int m = 0; m < 4; m++)
#pragma unroll
                    for (int n = 0; n < 2; n++) wmma::fill_fragment(acc[m][n], 0.f);
            }

            const __half* z = zb[c & 1];
#pragma unroll
            for (int k = 0; k < 4; k++) {
#pragma unroll
                for (int m = 0; m < 4; m++)
                    wmma::load_matrix_sync(a[m], z + (m0 + m * 16) * ZLDH + k * 16, ZLDH);
                wmma::load_matrix_sync(b0, sW + (p * 64 + k * 16) * WLDH + n0,      WLDH);
                wmma::load_matrix_sync(b1, sW + (p * 64 + k * 16) * WLDH + n0 + 16, WLDH);
#pragma unroll
                for (int m = 0; m < 4; m++) {
                    wmma::mma_sync(acc[m][0], a[m], b0, acc[m][0]);
                    wmma::mma_sync(acc[m][1], a[m], b1, acc[m][1]);
                }
            }
            __syncthreads();             // all warps done with zb[c&1]
            gather(c + 2);               // refill freed buffer (in flight)
        }

        // ---- tile epilogue: stream C to g_pre, fold stats from L2 ----
#pragma unroll
        for (int m = 0; m < 4; m++)
#pragma unroll
            for (int n = 0; n < 2; n++)
                wmma::store_matrix_sync(
                    g_pre + (size_t)(e0 + m0 + m * 16) * NOUT + n0 + n * 16,
                    acc[m][n], NOUT, wmma::mem_row_major);
        __syncthreads();                 // C visible block-wide

        const float* base = g_pre + (size_t)(e0 + sgrp * 64) * NOUT + scol;
#pragma unroll 8
        for (int e = 0; e < 64; e++) {
            float v = base[(size_t)e * NOUT];
            s_acc += v; q_acc += v * v;
        }
    }

    atomicAdd(&g_sum[scol],   s_acc);
    atomicAdd(&g_sumsq[scol], q_acc);
}

// ---------------------------------------------------------------------------
// PASS 1: streaming epilogue: BN fold + softplus*sigmoid + red.v4 scatter.
// ---------------------------------------------------------------------------
__global__ __launch_bounds__(256)
void pass1_kernel(const void* __restrict__ eidx,
                  float* __restrict__ out) {
    __shared__ float sBN[2 * NOUT];
    const int tid = threadIdx.x;
    if (tid < NOUT) sBN[tid] = g_scale[tid];
    else            sBN[128 + (tid - 128)] = g_shift[tid - 128];
    __syncthreads();

    long long i = (long long)blockIdx.x * 256 + tid;   // NE*16 total
    int e = (int)(i >> 4), q = (int)(i & 15);

    int dst;
    if (g_idx64) dst = (int)reinterpret_cast<const long long*>(eidx)[2ll * e + 1];
    else         dst = reinterpret_cast<const int*>(eidx)[2 * e + 1];

    const float* row = g_pre + (size_t)e * NOUT;
    float4 xc4 = *reinterpret_cast<const float4*>(row + q * 4);
    float4 xf4 = *reinterpret_cast<const float4*>(row + 64 + q * 4);
    float xc[4] = {xc4.x, xc4.y, xc4.z, xc4.w};
    float xf[4] = {xf4.x, xf4.y, xf4.z, xf4.w};

    float m[4];
#pragma unroll
    for (int u = 0; u < 4; u++) {
        int c = q * 4 + u;
        float vc = xc[u] * sBN[c]      + sBN[NOUT + c];
        float vf = xf[u] * sBN[64 + c] + sBN[NOUT + 64 + c];
        // softplus via MUFU: max(x,0) + log(1 + exp(-|x|))
        float sp = fmaxf(vc, 0.f) + __logf(1.f + __expf(-fabsf(vc)));
        float sg = __fdividef(1.f, 1.f + __expf(-vf));            // sigmoid
        m[u] = sp * sg;
    }
    float* ptr = out + (long long)dst * ND + q * 4;
    asm volatile("red.global.add.v4.f32 [%0], {%1,%2,%3,%4};"
                 :: "l"(ptr), "f"(m[0]), "f"(m[1]), "f"(m[2]), "f"(m[3])
                 : "memory");
}

// ---------------------------------------------------------------------------
extern "C" void kernel_launch(void* const* d_in, const int* in_sizes, int n_in,
                              void* d_out, int out_size) {
    const float* atom  = (const float*)d_in[0];
    const float* edgef = (const float*)d_in[1];
    const float* Wf    = (const float*)d_in[2];
    const float* gf    = (const float*)d_in[4];
    const float* bf    = (const float*)d_in[5];
    const float* Wc    = (const float*)d_in[6];
    const float* gc    = (const float*)d_in[8];
    const float* bc    = (const float*)d_in[9];
    const void*  eidx  = d_in[10];
    float* out = (float*)d_out;

    cudaFuncSetAttribute(pass0_kernel,
                         cudaFuncAttributeMaxDynamicSharedMemorySize,
                         SMEM0_BYTES);

    prep_kernel<<<2048, 256>>>(atom, edgef, Wf, Wc, (const int*)eidx, out);
    pass0_kernel<<<GRID0, THREADS0, SMEM0_BYTES>>>(eidx);
    finalize_kernel<<<1, 128>>>(gc, bc, gf, bf);
    pass1_kernel<<<(NE * 16) / 256, 256>>>(eidx, out);
}

// round 13
// speedup vs baseline: 1.3898x; 1.0430x over previous
#include <cuda_runtime.h>
#include <cuda_fp16.h>
#include <mma.h>
#include <math.h>
#include <stdint.h>

using namespace nvcuda;

#define NA 50000
#define NE 800000
#define ND 64
#define FULL 192
#define NOUT 128          // cols 0..63 = core, 64..127 = filter
#define ET 128            // edges per tile
#define NTILES (NE / ET)  // 6250
#define GRID0 296         // 2 persistent CTAs per SM
#define THREADS0 256
#define WLDH 136          // W smem leading dim (halves)
#define ZLDH 72           // z chunk leading dim (halves): 64 + 8 pad
#define BN_EPS 1e-5f

// dyn smem: W (192x136 h) + 3 z-chunks (128x72 h) + idx[2][2][128] + stats
#define SMEM0_BYTES ((FULL * WLDH + 3 * ET * ZLDH) * 2 + 4 * ET * 4 + 2 * NOUT * 4)

__device__ __align__(16) __half g_Wt_h[FULL * NOUT];   // Wt[k][o] half
__device__ __align__(16) __half g_atom_h[NA * ND];
__device__ __align__(16) __half g_edge_h[(size_t)NE * ND];
__device__ float g_sum[NOUT];
__device__ float g_sumsq[NOUT];
__device__ float g_scale[NOUT];
__device__ float g_shift[NOUT];
__device__ int   g_idx64;
__device__ float g_pre[(size_t)NE * NOUT];             // 409.6 MB scratch

__device__ __forceinline__ void cp_async16(void* sdst, const void* gsrc) {
    unsigned saddr = (unsigned)__cvta_generic_to_shared(sdst);
    asm volatile("cp.async.ca.shared.global [%0], [%1], 16;"
                 :: "r"(saddr), "l"(gsrc) : "memory");
}

// ---------------------------------------------------------------------------
// prep: out = atom copy; atom/edge/W -> half; zero stats; idx dtype sniff
// ---------------------------------------------------------------------------
__global__ void prep_kernel(const float* __restrict__ atom,
                            const float* __restrict__ edgef,
                            const float* __restrict__ Wf,
                            const float* __restrict__ Wc,
                            const int* __restrict__ eidx_i32,
                            float* __restrict__ out) {
    int tid = blockIdx.x * blockDim.x + threadIdx.x;
    int stride = gridDim.x * blockDim.x;

    for (int i = tid; i < (NA * ND) / 4; i += stride) {
        float4 v = reinterpret_cast<const float4*>(atom)[i];
        reinterpret_cast<float4*>(out)[i] = v;
        __half2* h = reinterpret_cast<__half2*>(g_atom_h) + 2 * i;
        h[0] = __floats2half2_rn(v.x, v.y);
        h[1] = __floats2half2_rn(v.z, v.w);
    }
    for (long long i = tid; i < ((long long)NE * ND) / 4; i += stride) {
        float4 v = reinterpret_cast<const float4*>(edgef)[i];
        __half2* h = reinterpret_cast<__half2*>(g_edge_h) + 2 * i;
        h[0] = __floats2half2_rn(v.x, v.y);
        h[1] = __floats2half2_rn(v.z, v.w);
    }
    for (int i = tid; i < FULL * NOUT; i += stride) {
        int k = i / NOUT, o = i % NOUT;
        float w = (o < ND) ? Wc[o * FULL + k] : Wf[(o - ND) * FULL + k];
        g_Wt_h[i] = __float2half_rn(w);   // bias cancels inside batchnorm
    }
    if (tid < NOUT) { g_sum[tid] = 0.f; g_sumsq[tid] = 0.f; }
    if (tid == 0) {
        int any = 0;
        for (int k = 0; k < 512; k++) any |= eidx_i32[2 * k + 1];
        g_idx64 = (any == 0) ? 1 : 0;   // int64 => zero high words
    }
}

// ---------------------------------------------------------------------------
__global__ void finalize_kernel(const float* __restrict__ gc,
                                const float* __restrict__ bc,
                                const float* __restrict__ gf,
                                const float* __restrict__ bf) {
    int c = threadIdx.x;
    if (c < NOUT) {
        float mean = g_sum[c] * (1.f / (float)NE);
        float var  = g_sumsq[c] * (1.f / (float)NE) - mean * mean;
        float inv  = rsqrtf(var + BN_EPS);
        float gamma = (c < ND) ? gc[c] : gf[c - ND];
        float beta  = (c < ND) ? bc[c] : bf[c - ND];
        g_scale[c] = inv * gamma;
        g_shift[c] = beta - mean * inv * gamma;
    }
}

// ---------------------------------------------------------------------------
// PASS 0: persistent fp16 GEMM, 296 blocks x 256 threads. W resident in
// smem. 128-edge tiles, K in 3 chunks of 64 halves (dst/src/edge), TRIPLE-
// buffered cp.async: one barrier per chunk, none in the epilogue. Warp =
// 64 edges (4 m frags) x 32 cols (2 n frags). Column stats computed from
// the accumulator registers (HMMA.16816 layout) via shfl + smem atomics.
// ---------------------------------------------------------------------------
__global__ __launch_bounds__(THREADS0, 2)
void pass0_kernel(const void* __restrict__ eidx) {
    extern __shared__ __align__(16) unsigned char smraw[];
    __half* sW = reinterpret_cast<__half*>(smraw);        // 192*136 halves
    __half* zb[3];
    zb[0] = sW + FULL * WLDH;                             // 128*72 halves each
    zb[1] = zb[0] + ET * ZLDH;
    zb[2] = zb[1] + ET * ZLDH;
    int* sSrc = reinterpret_cast<int*>(zb[2] + ET * ZLDH);   // [2][ET]
    int* sDst = sSrc + 2 * ET;
    float* sSum = reinterpret_cast<float*>(sDst + 2 * ET);   // [NOUT]
    float* sSq  = sSum + NOUT;

    const int tid  = threadIdx.x;
    const int lane = tid & 31;
    const int bid  = blockIdx.x;
    const int nt   = (NTILES - bid + GRID0 - 1) / GRID0;  // tiles bid + t*296
    const bool i64 = (g_idx64 != 0);

    auto stageIdx = [&](int t) {
        if (tid < ET && t < nt) {
            int slot = t & 1;
            long long e = ((long long)bid + (long long)t * GRID0) * ET + tid;
            if (i64) {
                const long long* p = reinterpret_cast<const long long*>(eidx);
                sSrc[slot * ET + tid] = (int)p[2 * e];
                sDst[slot * ET + tid] = (int)p[2 * e + 1];
            } else {
                const int* p = reinterpret_cast<const int*>(eidx);
                sSrc[slot * ET + tid] = p[2 * e];
                sDst[slot * ET + tid] = p[2 * e + 1];
            }
        }
    };
    // gather K-chunk c (tile t = c/3, phase p = c%3) into zb[c%3]; always commits
    auto gather = [&](int c) {
        int t = c / 3, p = c - 3 * t;
        if (t < nt) {
            int islot = t & 1;
            long long e0 = ((long long)bid + (long long)t * GRID0) * ET;
            __half* zbuf = zb[c % 3];
            for (int i = tid; i < ET * 8; i += THREADS0) {
                int e = i >> 3, q = i & 7;
                const __half* g;
                if (p == 0)      g = g_atom_h + (long long)sDst[islot*ET + e] * ND + q * 8;
                else if (p == 1) g = g_atom_h + (long long)sSrc[islot*ET + e] * ND + q * 8;
                else             g = g_edge_h + (e0 + e) * ND + q * 8;
                cp_async16(zbuf + e * ZLDH + q * 8, g);
            }
        }
        asm volatile("cp.async.commit_group;" ::: "memory");
    };

    // ---- prologue: idx0 + stats zero; W copy + chunk0 (grp 0); chunk1 (grp 1)
    stageIdx(0);
    if (tid < NOUT) { sSum[tid] = 0.f; sSq[tid] = 0.f; }
    __syncthreads();
    for (int i = tid; i < FULL * 16; i += THREADS0) {
        int k = i >> 4, q = i & 15;
        cp_async16(sW + k * WLDH + q * 8, g_Wt_h + k * NOUT + q * 8);
    }
    gather(0);          // W + chunk0 committed together
    gather(1);

    const int w  = tid >> 5;
    const int m0 = (w & 1) * 64;       // 4 m-fragments (64 edges)
    const int n0 = (w >> 1) * 32;      // 2 n-fragments (32 cols)

    wmma::fragment<wmma::matrix_a, 16, 16, 16, __half, wmma::row_major> a[4];
    wmma::fragment<wmma::matrix_b, 16, 16, 16, __half, wmma::row_major> b0, b1;
    wmma::fragment<wmma::accumulator, 16, 16, 16, float> acc[4][2];

    for (int t = 0; t < nt; t++) {
        long long e0 = ((long long)bid + (long long)t * GRID0) * ET;

#pragma unroll
        for (int p = 0; p < 3; p++) {
            const int c = 3 * t + p;
            asm volatile("cp.async.wait_group 1;" ::: "memory");
            __syncthreads();             // chunk c visible; zb[(c+2)%3] free

            if (p == 0) {
                stageIdx(t + 1);         // slot (t+1)&1; barrier at c+1 covers
#pragma unroll
                for (int m = 0; m < 4; m++)
#pragma unroll
                    for (int n = 0; n < 2; n++) wmma::fill_fragment(acc[m][n], 0.f);
            }

            const __half* z = zb[c % 3];
#pragma unroll
            for (int k = 0; k < 4; k++) {
#pragma unroll
                for (int m = 0; m < 4; m++)
                    wmma::load_matrix_sync(a[m], z + (m0 + m * 16) * ZLDH + k * 16, ZLDH);
                wmma::load_matrix_sync(b0, sW + (p * 64 + k * 16) * WLDH + n0,      WLDH);
                wmma::load_matrix_sync(b1, sW + (p * 64 + k * 16) * WLDH + n0 + 16, WLDH);
#pragma unroll
                for (int m = 0; m < 4; m++) {
                    wmma::mma_sync(acc[m][0], a[m], b0, acc[m][0]);
                    wmma::mma_sync(acc[m][1], a[m], b1, acc[m][1]);
                }
            }
            gather(c + 2);               // writes zb[(c+2)%3], freed above
        }

        // ---- tile epilogue (no barrier): C -> g_pre; stats from registers
#pragma unroll
        for (int m = 0; m < 4; m++)
#pragma unroll
            for (int n = 0; n < 2; n++)
                wmma::store_matrix_sync(
                    g_pre + (size_t)(e0 + m0 + m * 16) * NOUT + n0 + n * 16,
                    acc[m][n], NOUT, wmma::mem_row_major);

        // HMMA.16816 acc layout: x[0,1]=(g, c),(g, c+1); x[2,3]=rows+8;
        // x[4..7]=cols+8; g=lane>>2, c=(lane&3)*2.
#pragma unroll
        for (int n = 0; n < 2; n++) {
            float ps[4] = {0.f, 0.f, 0.f, 0.f};
            float qs[4] = {0.f, 0.f, 0.f, 0.f};
#pragma unroll
            for (int m = 0; m < 4; m++) {
                const float* x = acc[m][n].x;
                ps[0] += x[0] + x[2];  qs[0] += x[0]*x[0] + x[2]*x[2];
                ps[1] += x[1] + x[3];  qs[1] += x[1]*x[1] + x[3]*x[3];
                ps[2] += x[4] + x[6];  qs[2] += x[4]*x[4] + x[6]*x[6];
                ps[3] += x[5] + x[7];  qs[3] += x[5]*x[5] + x[7]*x[7];
            }
#pragma unroll
            for (int d = 4; d < 32; d <<= 1) {
#pragma unroll
                for (int u = 0; u < 4; u++) {
                    ps[u] += __shfl_xor_sync(0xFFFFFFFFu, ps[u], d);
                    qs[u] += __shfl_xor_sync(0xFFFFFFFFu, qs[u], d);
                }
            }
            if (lane < 4) {
                int cb = n0 + n * 16 + lane * 2;
                atomicAdd(&sSum[cb],     ps[0]);  atomicAdd(&sSq[cb],     qs[0]);
                atomicAdd(&sSum[cb + 1], ps[1]);  atomicAdd(&sSq[cb + 1], qs[1]);
                atomicAdd(&sSum[cb + 8], ps[2]);  atomicAdd(&sSq[cb + 8], qs[2]);
                atomicAdd(&sSum[cb + 9], ps[3]);  atomicAdd(&sSq[cb + 9], qs[3]);
            }
        }
    }

    __syncthreads();
    if (tid < NOUT) {
        atomicAdd(&g_sum[tid],   sSum[tid]);
        atomicAdd(&g_sumsq[tid], sSq[tid]);
    }
}

// ---------------------------------------------------------------------------
// PASS 1: streaming epilogue: BN fold + softplus*sigmoid + red.v4 scatter.
// ---------------------------------------------------------------------------
__global__ __launch_bounds__(256)
void pass1_kernel(const void* __restrict__ eidx,
                  float* __restrict__ out) {
    __shared__ float sBN[2 * NOUT];
    const int tid = threadIdx.x;
    if (tid < NOUT) sBN[tid] = g_scale[tid];
    else            sBN[128 + (tid - 128)] = g_shift[tid - 128];
    __syncthreads();

    long long i = (long long)blockIdx.x * 256 + tid;   // NE*16 total
    int e = (int)(i >> 4), q = (int)(i & 15);

    int dst;
    if (g_idx64) dst = (int)reinterpret_cast<const long long*>(eidx)[2ll * e + 1];
    else         dst = reinterpret_cast<const int*>(eidx)[2 * e + 1];

    const float* row = g_pre + (size_t)e * NOUT;
    float4 xc4 = *reinterpret_cast<const float4*>(row + q * 4);
    float4 xf4 = *reinterpret_cast<const float4*>(row + 64 + q * 4);
    float xc[4] = {xc4.x, xc4.y, xc4.z, xc4.w};
    float xf[4] = {xf4.x, xf4.y, xf4.z, xf4.w};

    float m[4];
#pragma unroll
    for (int u = 0; u < 4; u++) {
        int c = q * 4 + u;
        float vc = xc[u] * sBN[c]      + sBN[NOUT + c];
        float vf = xf[u] * sBN[64 + c] + sBN[NOUT + 64 + c];
        // softplus via MUFU: max(x,0) + log(1 + exp(-|x|))
        float sp = fmaxf(vc, 0.f) + __logf(1.f + __expf(-fabsf(vc)));
        float sg = __fdividef(1.f, 1.f + __expf(-vf));            // sigmoid
        m[u] = sp * sg;
    }
    float* ptr = out + (long long)dst * ND + q * 4;
    asm volatile("red.global.add.v4.f32 [%0], {%1,%2,%3,%4};"
                 :: "l"(ptr), "f"(m[0]), "f"(m[1]), "f"(m[2]), "f"(m[3])
                 : "memory");
}

// ---------------------------------------------------------------------------
extern "C" void kernel_launch(void* const* d_in, const int* in_sizes, int n_in,
                              void* d_out, int out_size) {
    const float* atom  = (const float*)d_in[0];
    const float* edgef = (const float*)d_in[1];
    const float* Wf    = (const float*)d_in[2];
    const float* gf    = (const float*)d_in[4];
    const float* bf    = (const float*)d_in[5];
    const float* Wc    = (const float*)d_in[6];
    const float* gc    = (const float*)d_in[8];
    const float* bc    = (const float*)d_in[9];
    const void*  eidx  = d_in[10];
    float* out = (float*)d_out;

    cudaFuncSetAttribute(pass0_kernel,
                         cudaFuncAttributeMaxDynamicSharedMemorySize,
                         SMEM0_BYTES);

    prep_kernel<<<2048, 256>>>(atom, edgef, Wf, Wc, (const int*)eidx, out);
    pass0_kernel<<<GRID0, THREADS0, SMEM0_BYTES>>>(eidx);
    finalize_kernel<<<1, 128>>>(gc, bc, gf, bf);
    pass1_kernel<<<(NE * 16) / 256, 256>>>(eidx, out);
}

// round 14
// speedup vs baseline: 1.4725x; 1.0595x over previous
#include <cuda_runtime.h>
#include <cuda_fp16.h>
#include <mma.h>
#include <math.h>
#include <stdint.h>

using namespace nvcuda;

#define NA 50000
#define NE 800000
#define ND 64
#define FULL 192
#define NOUT 128          // cols 0..63 = core, 64..127 = filter
#define ET 128            // edges per tile
#define NTILES (NE / ET)  // 6250
#define GRID0 296         // 2 persistent CTAs per SM
#define THREADS0 256
#define WLDH 136          // W smem leading dim (halves)
#define ZLDH 72           // z chunk leading dim (halves): 64 + 8 pad
#define BN_EPS 1e-5f

// dyn smem: W (192x136 h) + 3 z-chunks (128x72 h) + idx[2][2][128] + stats
#define SMEM0_BYTES ((FULL * WLDH + 3 * ET * ZLDH) * 2 + 4 * ET * 4 + 2 * NOUT * 4)

__device__ __align__(16) __half g_Wt_h[FULL * NOUT];   // Wt[k][o] half
__device__ __align__(16) __half g_atom_h[NA * ND];
__device__ float g_sum[NOUT];
__device__ float g_sumsq[NOUT];
__device__ float g_scale[NOUT];
__device__ float g_shift[NOUT];
__device__ int   g_idx64;
__device__ __align__(16) __half g_pre_h[(size_t)NE * NOUT];  // 204.8 MB scratch

__device__ __forceinline__ void cp_async16(void* sdst, const void* gsrc) {
    unsigned saddr = (unsigned)__cvta_generic_to_shared(sdst);
    asm volatile("cp.async.ca.shared.global [%0], [%1], 16;"
                 :: "r"(saddr), "l"(gsrc) : "memory");
}

// ---------------------------------------------------------------------------
// prep: out = atom copy; atom/W -> half; zero stats; idx dtype sniff.
// (edge features are read as f32 directly by pass0 — no pre-conversion)
// ---------------------------------------------------------------------------
__global__ void prep_kernel(const float* __restrict__ atom,
                            const float* __restrict__ Wf,
                            const float* __restrict__ Wc,
                            const int* __restrict__ eidx_i32,
                            float* __restrict__ out) {
    int tid = blockIdx.x * blockDim.x + threadIdx.x;
    int stride = gridDim.x * blockDim.x;

    for (int i = tid; i < (NA * ND) / 4; i += stride) {
        float4 v = reinterpret_cast<const float4*>(atom)[i];
        reinterpret_cast<float4*>(out)[i] = v;
        __half2* h = reinterpret_cast<__half2*>(g_atom_h) + 2 * i;
        h[0] = __floats2half2_rn(v.x, v.y);
        h[1] = __floats2half2_rn(v.z, v.w);
    }
    for (int i = tid; i < FULL * NOUT; i += stride) {
        int k = i / NOUT, o = i % NOUT;
        float w = (o < ND) ? Wc[o * FULL + k] : Wf[(o - ND) * FULL + k];
        g_Wt_h[i] = __float2half_rn(w);   // bias cancels inside batchnorm
    }
    if (tid < NOUT) { g_sum[tid] = 0.f; g_sumsq[tid] = 0.f; }
    if (tid == 0) {
        int any = 0;
        for (int k = 0; k < 512; k++) any |= eidx_i32[2 * k + 1];
        g_idx64 = (any == 0) ? 1 : 0;   // int64 => zero high words
    }
}

// ---------------------------------------------------------------------------
__global__ void finalize_kernel(const float* __restrict__ gc,
                                const float* __restrict__ bc,
                                const float* __restrict__ gf,
                                const float* __restrict__ bf) {
    int c = threadIdx.x;
    if (c < NOUT) {
        float mean = g_sum[c] * (1.f / (float)NE);
        float var  = g_sumsq[c] * (1.f / (float)NE) - mean * mean;
        float inv  = rsqrtf(var + BN_EPS);
        float gamma = (c < ND) ? gc[c] : gf[c - ND];
        float beta  = (c < ND) ? bc[c] : bf[c - ND];
        g_scale[c] = inv * gamma;
        g_shift[c] = beta - mean * inv * gamma;
    }
}

// ---------------------------------------------------------------------------
// PASS 0: persistent fp16 GEMM, 296 blocks x 256 threads. W resident in
// smem. 128-edge tiles, K in 3 chunks of 64 halves (dst/src via cp.async of
// pre-converted halves; edge via direct f32 LDG + cvt + STS), TRIPLE-
// buffered: one barrier per chunk, none in the epilogue. Warp = 64 edges
// (4 m frags) x 32 cols (2 n frags). Pre-activations packed to half2 and
// stored straight from accumulator registers; column stats from registers
// (HMMA.16816 layout) via shfl + smem atomics.
// ---------------------------------------------------------------------------
__global__ __launch_bounds__(THREADS0, 2)
void pass0_kernel(const float* __restrict__ edgef,
                  const void*  __restrict__ eidx) {
    extern __shared__ __align__(16) unsigned char smraw[];
    __half* sW = reinterpret_cast<__half*>(smraw);        // 192*136 halves
    __half* zb[3];
    zb[0] = sW + FULL * WLDH;                             // 128*72 halves each
    zb[1] = zb[0] + ET * ZLDH;
    zb[2] = zb[1] + ET * ZLDH;
    int* sSrc = reinterpret_cast<int*>(zb[2] + ET * ZLDH);   // [2][ET]
    int* sDst = sSrc + 2 * ET;
    float* sSum = reinterpret_cast<float*>(sDst + 2 * ET);   // [NOUT]
    float* sSq  = sSum + NOUT;

    const int tid  = threadIdx.x;
    const int lane = tid & 31;
    const int bid  = blockIdx.x;
    const int nt   = (NTILES - bid + GRID0 - 1) / GRID0;  // tiles bid + t*296
    const bool i64 = (g_idx64 != 0);

    auto stageIdx = [&](int t) {
        if (tid < ET && t < nt) {
            int slot = t & 1;
            long long e = ((long long)bid + (long long)t * GRID0) * ET + tid;
            if (i64) {
                const long long* p = reinterpret_cast<const long long*>(eidx);
                sSrc[slot * ET + tid] = (int)p[2 * e];
                sDst[slot * ET + tid] = (int)p[2 * e + 1];
            } else {
                const int* p = reinterpret_cast<const int*>(eidx);
                sSrc[slot * ET + tid] = p[2 * e];
                sDst[slot * ET + tid] = p[2 * e + 1];
            }
        }
    };
    // gather K-chunk c (tile t = c/3, phase p = c%3) into zb[c%3].
    // p<2: cp.async of pre-converted halves. p==2: f32 LDG + cvt + STS.
    // Always commits a group (possibly empty) to keep wait_group counts aligned.
    auto gather = [&](int c) {
        int t = c / 3, p = c - 3 * t;
        if (t < nt) {
            int islot = t & 1;
            long long e0 = ((long long)bid + (long long)t * GRID0) * ET;
            __half* zbuf = zb[c % 3];
            if (p < 2) {
                for (int i = tid; i < ET * 8; i += THREADS0) {
                    int e = i >> 3, q = i & 7;
                    const __half* g = (p == 0)
                        ? g_atom_h + (long long)sDst[islot*ET + e] * ND + q * 8
                        : g_atom_h + (long long)sSrc[islot*ET + e] * ND + q * 8;
                    cp_async16(zbuf + e * ZLDH + q * 8, g);
                }
            } else {
                for (int i = tid; i < ET * 8; i += THREADS0) {
                    int e = i >> 3, q = i & 7;   // 8 halves per task
                    const float4* gp = reinterpret_cast<const float4*>(
                        edgef + (e0 + e) * ND + q * 8);
                    float4 v0 = gp[0], v1 = gp[1];
                    __half2 h[4];
                    h[0] = __floats2half2_rn(v0.x, v0.y);
                    h[1] = __floats2half2_rn(v0.z, v0.w);
                    h[2] = __floats2half2_rn(v1.x, v1.y);
                    h[3] = __floats2half2_rn(v1.z, v1.w);
                    *reinterpret_cast<uint4*>(zbuf + e * ZLDH + q * 8)
                        = *reinterpret_cast<uint4*>(h);
                }
            }
        }
        asm volatile("cp.async.commit_group;" ::: "memory");
    };

    // ---- prologue: idx0 + stats zero; W copy + chunk0 (grp 0); chunk1 (grp 1)
    stageIdx(0);
    if (tid < NOUT) { sSum[tid] = 0.f; sSq[tid] = 0.f; }
    __syncthreads();
    for (int i = tid; i < FULL * 16; i += THREADS0) {
        int k = i >> 4, q = i & 15;
        cp_async16(sW + k * WLDH + q * 8, g_Wt_h + k * NOUT + q * 8);
    }
    gather(0);          // W + chunk0 committed together
    gather(1);

    const int w  = tid >> 5;
    const int m0 = (w & 1) * 64;       // 4 m-fragments (64 edges)
    const int n0 = (w >> 1) * 32;      // 2 n-fragments (32 cols)
    const int g  = lane >> 2;          // acc row within 8
    const int cc = (lane & 3) * 2;     // acc col pair base

    wmma::fragment<wmma::matrix_a, 16, 16, 16, __half, wmma::row_major> a[4];
    wmma::fragment<wmma::matrix_b, 16, 16, 16, __half, wmma::row_major> b0, b1;
    wmma::fragment<wmma::accumulator, 16, 16, 16, float> acc[4][2];

    for (int t = 0; t < nt; t++) {
        long long e0 = ((long long)bid + (long long)t * GRID0) * ET;

#pragma unroll
        for (int p = 0; p < 3; p++) {
            const int c = 3 * t + p;
            asm volatile("cp.async.wait_group 1;" ::: "memory");
            __syncthreads();             // chunk c visible; zb[(c+2)%3] free

            if (p == 0) {
                stageIdx(t + 1);         // slot (t+1)&1; barrier at c+1 covers
#pragma unroll
                for (int m = 0; m < 4; m++)
#pragma unroll
                    for (int n = 0; n < 2; n++) wmma::fill_fragment(acc[m][n], 0.f);
            }

            const __half* z = zb[c % 3];
#pragma unroll
            for (int k = 0; k < 4; k++) {
#pragma unroll
                for (int m = 0; m < 4; m++)
                    wmma::load_matrix_sync(a[m], z + (m0 + m * 16) * ZLDH + k * 16, ZLDH);
                wmma::load_matrix_sync(b0, sW + (p * 64 + k * 16) * WLDH + n0,      WLDH);
                wmma::load_matrix_sync(b1, sW + (p * 64 + k * 16) * WLDH + n0 + 16, WLDH);
#pragma unroll
                for (int m = 0; m < 4; m++) {
                    wmma::mma_sync(acc[m][0], a[m], b0, acc[m][0]);
                    wmma::mma_sync(acc[m][1], a[m], b1, acc[m][1]);
                }
            }
            gather(c + 2);               // writes zb[(c+2)%3], freed above
        }

        // ---- tile epilogue (no barrier): acc regs -> half2 -> g_pre_h.
        // HMMA.16816 acc layout: x[0,1]=(g,cc),(g,cc+1); x[2,3]=rows+8;
        // x[4..7]=cols+8; g=lane>>2, cc=(lane&3)*2.
#pragma unroll
        for (int m = 0; m < 4; m++) {
            size_t rb = (size_t)(e0 + m0 + m * 16);
#pragma unroll
            for (int n = 0; n < 2; n++) {
                const float* x = acc[m][n].x;
                int col = n0 + n * 16 + cc;
                *reinterpret_cast<__half2*>(g_pre_h + (rb + g) * NOUT + col)
                    = __floats2half2_rn(x[0], x[1]);
                *reinterpret_cast<__half2*>(g_pre_h + (rb + g + 8) * NOUT + col)
                    = __floats2half2_rn(x[2], x[3]);
                *reinterpret_cast<__half2*>(g_pre_h + (rb + g) * NOUT + col + 8)
                    = __floats2half2_rn(x[4], x[5]);
                *reinterpret_cast<__half2*>(g_pre_h + (rb + g + 8) * NOUT + col + 8)
                    = __floats2half2_rn(x[6], x[7]);
            }
        }

        // ---- stats from f32 registers (shfl reduce + smem atomics) ----
#pragma unroll
        for (int n = 0; n < 2; n++) {
            float ps[4] = {0.f, 0.f, 0.f, 0.f};
            float qs[4] = {0.f, 0.f, 0.f, 0.f};
#pragma unroll
            for (int m = 0; m < 4; m++) {
                const float* x = acc[m][n].x;
                ps[0] += x[0] + x[2];  qs[0] += x[0]*x[0] + x[2]*x[2];
                ps[1] += x[1] + x[3];  qs[1] += x[1]*x[1] + x[3]*x[3];
                ps[2] += x[4] + x[6];  qs[2] += x[4]*x[4] + x[6]*x[6];
                ps[3] += x[5] + x[7];  qs[3] += x[5]*x[5] + x[7]*x[7];
            }
#pragma unroll
            for (int d = 4; d < 32; d <<= 1) {
#pragma unroll
                for (int u = 0; u < 4; u++) {
                    ps[u] += __shfl_xor_sync(0xFFFFFFFFu, ps[u], d);
                    qs[u] += __shfl_xor_sync(0xFFFFFFFFu, qs[u], d);
                }
            }
            if (lane < 4) {
                int cb = n0 + n * 16 + lane * 2;
                atomicAdd(&sSum[cb],     ps[0]);  atomicAdd(&sSq[cb],     qs[0]);
                atomicAdd(&sSum[cb + 1], ps[1]);  atomicAdd(&sSq[cb + 1], qs[1]);
                atomicAdd(&sSum[cb + 8], ps[2]);  atomicAdd(&sSq[cb + 8], qs[2]);
                atomicAdd(&sSum[cb + 9], ps[3]);  atomicAdd(&sSq[cb + 9], qs[3]);
            }
        }
    }

    __syncthreads();
    if (tid < NOUT) {
        atomicAdd(&g_sum[tid],   sSum[tid]);
        atomicAdd(&g_sumsq[tid], sSq[tid]);
    }
}

// ---------------------------------------------------------------------------
// PASS 1: streaming epilogue over half pre-acts: BN + softplus*sigmoid +
// red.v4 scatter to out[dst].
// ---------------------------------------------------------------------------
__global__ __launch_bounds__(256)
void pass1_kernel(const void* __restrict__ eidx,
                  float* __restrict__ out) {
    __shared__ float sBN[2 * NOUT];
    const int tid = threadIdx.x;
    if (tid < NOUT) sBN[tid] = g_scale[tid];
    else            sBN[128 + (tid - 128)] = g_shift[tid - 128];
    __syncthreads();

    long long i = (long long)blockIdx.x * 256 + tid;   // NE*16 total
    int e = (int)(i >> 4), q = (int)(i & 15);

    int dst;
    if (g_idx64) dst = (int)reinterpret_cast<const long long*>(eidx)[2ll * e + 1];
    else         dst = reinterpret_cast<const int*>(eidx)[2 * e + 1];

    const __half* row = g_pre_h + (size_t)e * NOUT;
    __half2 hc[2], hf[2];
    *reinterpret_cast<uint2*>(hc) = *reinterpret_cast<const uint2*>(row + q * 4);
    *reinterpret_cast<uint2*>(hf) = *reinterpret_cast<const uint2*>(row + 64 + q * 4);
    float2 c01 = __half22float2(hc[0]), c23 = __half22float2(hc[1]);
    float2 f01 = __half22float2(hf[0]), f23 = __half22float2(hf[1]);
    float xc[4] = {c01.x, c01.y, c23.x, c23.y};
    float xf[4] = {f01.x, f01.y, f23.x, f23.y};

    float m[4];
#pragma unroll
    for (int u = 0; u < 4; u++) {
        int c = q * 4 + u;
        float vc = xc[u] * sBN[c]      + sBN[NOUT + c];
        float vf = xf[u] * sBN[64 + c] + sBN[NOUT + 64 + c];
        // softplus via MUFU: max(x,0) + log(1 + exp(-|x|))
        float sp = fmaxf(vc, 0.f) + __logf(1.f + __expf(-fabsf(vc)));
        float sg = __fdividef(1.f, 1.f + __expf(-vf));            // sigmoid
        m[u] = sp * sg;
    }
    float* ptr = out + (long long)dst * ND + q * 4;
    asm volatile("red.global.add.v4.f32 [%0], {%1,%2,%3,%4};"
                 :: "l"(ptr), "f"(m[0]), "f"(m[1]), "f"(m[2]), "f"(m[3])
                 : "memory");
}

// ---------------------------------------------------------------------------
extern "C" void kernel_launch(void* const* d_in, const int* in_sizes, int n_in,
                              void* d_out, int out_size) {
    const float* atom  = (const float*)d_in[0];
    const float* edgef = (const float*)d_in[1];
    const float* Wf    = (const float*)d_in[2];
    const float* gf    = (const float*)d_in[4];
    const float* bf    = (const float*)d_in[5];
    const float* Wc    = (const float*)d_in[6];
    const float* gc    = (const float*)d_in[8];
    const float* bc    = (const float*)d_in[9];
    const void*  eidx  = d_in[10];
    float* out = (float*)d_out;

    cudaFuncSetAttribute(pass0_kernel,
                         cudaFuncAttributeMaxDynamicSharedMemorySize,
                         SMEM0_BYTES);

    prep_kernel<<<2048, 256>>>(atom, Wf, Wc, (const int*)eidx, out);
    pass0_kernel<<<GRID0, THREADS0, SMEM0_BYTES>>>(edgef, eidx);
    finalize_kernel<<<1, 128>>>(gc, bc, gf, bf);
    pass1_kernel<<<(NE * 16) / 256, 256>>>(eidx, out);
}

// round 15
// speedup vs baseline: 1.5240x; 1.0350x over previous
#include <cuda_runtime.h>
#include <cuda_fp16.h>
#include <mma.h>
#include <math.h>
#include <stdint.h>

using namespace nvcuda;

#define NA 50000
#define NE 800000
#define ND 64
#define FULL 192
#define NOUT 128          // cols 0..63 = core, 64..127 = filter
#define ET 128            // edges per tile
#define NTILES (NE / ET)  // 6250
#define GRID0 296         // 2 persistent CTAs per SM
#define THREADS0 256
#define WLDH 136          // W smem leading dim (halves)
#define ZLDH 72           // z chunk leading dim (halves): 64 + 8 pad
#define BN_EPS 1e-5f

// dyn smem: W (192x136 h) + 3 z-chunks (128x72 h) + idx[2][2][128] + stats
#define SMEM0_BYTES ((FULL * WLDH + 3 * ET * ZLDH) * 2 + 4 * ET * 4 + 2 * NOUT * 4)

__device__ __align__(16) __half g_Wt_h[FULL * NOUT];   // Wt[k][o] half
__device__ __align__(16) __half g_atom_h[NA * ND];
__device__ float g_sum[NOUT];
__device__ float g_sumsq[NOUT];
__device__ float g_scale[NOUT];
__device__ float g_shift[NOUT];
__device__ int   g_idx64;
__device__ __align__(16) __half g_pre_h[(size_t)NE * NOUT];  // 204.8 MB scratch

__device__ __forceinline__ void cp_async16(void* sdst, const void* gsrc) {
    unsigned saddr = (unsigned)__cvta_generic_to_shared(sdst);
    asm volatile("cp.async.ca.shared.global [%0], [%1], 16;"
                 :: "r"(saddr), "l"(gsrc) : "memory");
}

// ---------------------------------------------------------------------------
// prep: out = atom copy; atom/W -> half; zero stats; idx dtype sniff.
// (edge features are read as f32 directly by pass0 — no pre-conversion)
// ---------------------------------------------------------------------------
__global__ void prep_kernel(const float* __restrict__ atom,
                            const float* __restrict__ Wf,
                            const float* __restrict__ Wc,
                            const int* __restrict__ eidx_i32,
                            float* __restrict__ out) {
    int tid = blockIdx.x * blockDim.x + threadIdx.x;
    int stride = gridDim.x * blockDim.x;

    for (int i = tid; i < (NA * ND) / 4; i += stride) {
        float4 v = reinterpret_cast<const float4*>(atom)[i];
        reinterpret_cast<float4*>(out)[i] = v;
        __half2* h = reinterpret_cast<__half2*>(g_atom_h) + 2 * i;
        h[0] = __floats2half2_rn(v.x, v.y);
        h[1] = __floats2half2_rn(v.z, v.w);
    }
    for (int i = tid; i < FULL * NOUT; i += stride) {
        int k = i / NOUT, o = i % NOUT;
        float w = (o < ND) ? Wc[o * FULL + k] : Wf[(o - ND) * FULL + k];
        g_Wt_h[i] = __float2half_rn(w);   // bias cancels inside batchnorm
    }
    if (tid < NOUT) { g_sum[tid] = 0.f; g_sumsq[tid] = 0.f; }
    if (tid == 0) {
        int any = 0;
        for (int k = 0; k < 512; k++) any |= eidx_i32[2 * k + 1];
        g_idx64 = (any == 0) ? 1 : 0;   // int64 => zero high words
    }
}

// ---------------------------------------------------------------------------
__global__ void finalize_kernel(const float* __restrict__ gc,
                                const float* __restrict__ bc,
                                const float* __restrict__ gf,
                                const float* __restrict__ bf) {
    int c = threadIdx.x;
    if (c < NOUT) {
        float mean = g_sum[c] * (1.f / (float)NE);
        float var  = g_sumsq[c] * (1.f / (float)NE) - mean * mean;
        float inv  = rsqrtf(var + BN_EPS);
        float gamma = (c < ND) ? gc[c] : gf[c - ND];
        float beta  = (c < ND) ? bc[c] : bf[c - ND];
        g_scale[c] = inv * gamma;
        g_shift[c] = beta - mean * inv * gamma;
    }
}

// ---------------------------------------------------------------------------
// PASS 0: persistent fp16 GEMM, 296 blocks x 256 threads. W resident in
// smem. 128-edge tiles, K in 3 chunks of 64 halves (dst/src via cp.async of
// pre-converted halves; edge via BATCHED f32 LDG (MLP=8) + cvt + STS),
// triple-buffered: one barrier per chunk, none in the epilogue. Warp =
// 64 edges (4 m frags) x 32 cols (2 n frags). Pre-activations packed to
// half2 and stored straight from accumulator registers; column stats from
// registers (HMMA.16816 layout) via shfl + smem atomics.
// ---------------------------------------------------------------------------
__global__ __launch_bounds__(THREADS0, 2)
void pass0_kernel(const float* __restrict__ edgef,
                  const void*  __restrict__ eidx) {
    extern __shared__ __align__(16) unsigned char smraw[];
    __half* sW = reinterpret_cast<__half*>(smraw);        // 192*136 halves
    __half* zb[3];
    zb[0] = sW + FULL * WLDH;                             // 128*72 halves each
    zb[1] = zb[0] + ET * ZLDH;
    zb[2] = zb[1] + ET * ZLDH;
    int* sSrc = reinterpret_cast<int*>(zb[2] + ET * ZLDH);   // [2][ET]
    int* sDst = sSrc + 2 * ET;
    float* sSum = reinterpret_cast<float*>(sDst + 2 * ET);   // [NOUT]
    float* sSq  = sSum + NOUT;

    const int tid  = threadIdx.x;
    const int lane = tid & 31;
    const int bid  = blockIdx.x;
    const int nt   = (NTILES - bid + GRID0 - 1) / GRID0;  // tiles bid + t*296
    const bool i64 = (g_idx64 != 0);

    auto stageIdx = [&](int t) {
        if (tid < ET && t < nt) {
            int slot = t & 1;
            long long e = ((long long)bid + (long long)t * GRID0) * ET + tid;
            if (i64) {
                const long long* p = reinterpret_cast<const long long*>(eidx);
                sSrc[slot * ET + tid] = (int)p[2 * e];
                sDst[slot * ET + tid] = (int)p[2 * e + 1];
            } else {
                const int* p = reinterpret_cast<const int*>(eidx);
                sSrc[slot * ET + tid] = p[2 * e];
                sDst[slot * ET + tid] = p[2 * e + 1];
            }
        }
    };
    // gather K-chunk c (tile t = c/3, phase p = c%3) into zb[c%3].
    // p<2: cp.async of pre-converted halves (fire-and-forget).
    // p==2: batched f32 LDGs (8 x LDG.128 in flight) then cvt + STS.
    // Always commits a group (possibly empty) to keep wait_group counts aligned.
    auto gather = [&](int c) {
        int t = c / 3, p = c - 3 * t;
        if (t < nt) {
            int islot = t & 1;
            long long e0 = ((long long)bid + (long long)t * GRID0) * ET;
            __half* zbuf = zb[c % 3];
            if (p < 2) {
                for (int i = tid; i < ET * 8; i += THREADS0) {
                    int e = i >> 3, q = i & 7;
                    const __half* g = (p == 0)
                        ? g_atom_h + (long long)sDst[islot*ET + e] * ND + q * 8
                        : g_atom_h + (long long)sSrc[islot*ET + e] * ND + q * 8;
                    cp_async16(zbuf + e * ZLDH + q * 8, g);
                }
            } else {
                // ET*8 = 1024 tasks / 256 threads = exactly 4 per thread
                float4 v[8];
#pragma unroll
                for (int j = 0; j < 4; j++) {
                    int i = tid + j * THREADS0;
                    int e = i >> 3, q = i & 7;
                    const float4* gp = reinterpret_cast<const float4*>(
                        edgef + (e0 + e) * ND + q * 8);
                    v[2*j]   = gp[0];
                    v[2*j+1] = gp[1];
                }
#pragma unroll
                for (int j = 0; j < 4; j++) {
                    int i = tid + j * THREADS0;
                    int e = i >> 3, q = i & 7;
                    __half2 h[4];
                    h[0] = __floats2half2_rn(v[2*j].x,   v[2*j].y);
                    h[1] = __floats2half2_rn(v[2*j].z,   v[2*j].w);
                    h[2] = __floats2half2_rn(v[2*j+1].x, v[2*j+1].y);
                    h[3] = __floats2half2_rn(v[2*j+1].z, v[2*j+1].w);
                    *reinterpret_cast<uint4*>(zbuf + e * ZLDH + q * 8)
                        = *reinterpret_cast<uint4*>(h);
                }
            }
        }
        asm volatile("cp.async.commit_group;" ::: "memory");
    };

    // ---- prologue: idx0 + stats zero; W copy + chunk0 (grp 0); chunk1 (grp 1)
    stageIdx(0);
    if (tid < NOUT) { sSum[tid] = 0.f; sSq[tid] = 0.f; }
    __syncthreads();
    for (int i = tid; i < FULL * 16; i += THREADS0) {
        int k = i >> 4, q = i & 15;
        cp_async16(sW + k * WLDH + q * 8, g_Wt_h + k * NOUT + q * 8);
    }
    gather(0);          // W + chunk0 committed together
    gather(1);

    const int w  = tid >> 5;
    const int m0 = (w & 1) * 64;       // 4 m-fragments (64 edges)
    const int n0 = (w >> 1) * 32;      // 2 n-fragments (32 cols)
    const int g  = lane >> 2;          // acc row within 8
    const int cc = (lane & 3) * 2;     // acc col pair base

    wmma::fragment<wmma::matrix_a, 16, 16, 16, __half, wmma::row_major> a[4];
    wmma::fragment<wmma::matrix_b, 16, 16, 16, __half, wmma::row_major> b0, b1;
    wmma::fragment<wmma::accumulator, 16, 16, 16, float> acc[4][2];

    for (int t = 0; t < nt; t++) {
        long long e0 = ((long long)bid + (long long)t * GRID0) * ET;

#pragma unroll
        for (int p = 0; p < 3; p++) {
            const int c = 3 * t + p;
            asm volatile("cp.async.wait_group 1;" ::: "memory");
            __syncthreads();             // chunk c visible; zb[(c+2)%3] free

            if (p == 0) {
                stageIdx(t + 1);         // slot (t+1)&1; barrier at c+1 covers
#pragma unroll
                for (int m = 0; m < 4; m++)
#pragma unroll
                    for (int n = 0; n < 2; n++) wmma::fill_fragment(acc[m][n], 0.f);
            }

            const __half* z = zb[c % 3];
#pragma unroll
            for (int k = 0; k < 4; k++) {
#pragma unroll
                for (int m = 0; m < 4; m++)
                    wmma::load_matrix_sync(a[m], z + (m0 + m * 16) * ZLDH + k * 16, ZLDH);
                wmma::load_matrix_sync(b0, sW + (p * 64 + k * 16) * WLDH + n0,      WLDH);
                wmma::load_matrix_sync(b1, sW + (p * 64 + k * 16) * WLDH + n0 + 16, WLDH);
#pragma unroll
                for (int m = 0; m < 4; m++) {
                    wmma::mma_sync(acc[m][0], a[m], b0, acc[m][0]);
                    wmma::mma_sync(acc[m][1], a[m], b1, acc[m][1]);
                }
            }
            gather(c + 2);               // writes zb[(c+2)%3], freed above
        }

        // ---- tile epilogue (no barrier): acc regs -> half2 -> g_pre_h.
        // HMMA.16816 acc layout: x[0,1]=(g,cc),(g,cc+1); x[2,3]=rows+8;
        // x[4..7]=cols+8; g=lane>>2, cc=(lane&3)*2.
#pragma unroll
        for (int m = 0; m < 4; m++) {
            size_t rb = (size_t)(e0 + m0 + m * 16);
#pragma unroll
            for (int n = 0; n < 2; n++) {
                const float* x = acc[m][n].x;
                int col = n0 + n * 16 + cc;
                *reinterpret_cast<__half2*>(g_pre_h + (rb + g) * NOUT + col)
                    = __floats2half2_rn(x[0], x[1]);
                *reinterpret_cast<__half2*>(g_pre_h + (rb + g + 8) * NOUT + col)
                    = __floats2half2_rn(x[2], x[3]);
                *reinterpret_cast<__half2*>(g_pre_h + (rb + g) * NOUT + col + 8)
                    = __floats2half2_rn(x[4], x[5]);
                *reinterpret_cast<__half2*>(g_pre_h + (rb + g + 8) * NOUT + col + 8)
                    = __floats2half2_rn(x[6], x[7]);
            }
        }

        // ---- stats from f32 registers (shfl reduce + smem atomics) ----
#pragma unroll
        for (int n = 0; n < 2; n++) {
            float ps[4] = {0.f, 0.f, 0.f, 0.f};
            float qs[4] = {0.f, 0.f, 0.f, 0.f};
#pragma unroll
            for (int m = 0; m < 4; m++) {
                const float* x = acc[m][n].x;
                ps[0] += x[0] + x[2];  qs[0] += x[0]*x[0] + x[2]*x[2];
                ps[1] += x[1] + x[3];  qs[1] += x[1]*x[1] + x[3]*x[3];
                ps[2] += x[4] + x[6];  qs[2] += x[4]*x[4] + x[6]*x[6];
                ps[3] += x[5] + x[7];  qs[3] += x[5]*x[5] + x[7]*x[7];
            }
#pragma unroll
            for (int d = 4; d < 32; d <<= 1) {
#pragma unroll
                for (int u = 0; u < 4; u++) {
                    ps[u] += __shfl_xor_sync(0xFFFFFFFFu, ps[u], d);
                    qs[u] += __shfl_xor_sync(0xFFFFFFFFu, qs[u], d);
                }
            }
            if (lane < 4) {
                int cb = n0 + n * 16 + lane * 2;
                atomicAdd(&sSum[cb],     ps[0]);  atomicAdd(&sSq[cb],     qs[0]);
                atomicAdd(&sSum[cb + 1], ps[1]);  atomicAdd(&sSq[cb + 1], qs[1]);
                atomicAdd(&sSum[cb + 8], ps[2]);  atomicAdd(&sSq[cb + 8], qs[2]);
                atomicAdd(&sSum[cb + 9], ps[3]);  atomicAdd(&sSq[cb + 9], qs[3]);
            }
        }
    }

    __syncthreads();
    if (tid < NOUT) {
        atomicAdd(&g_sum[tid],   sSum[tid]);
        atomicAdd(&g_sumsq[tid], sSq[tid]);
    }
}

// ---------------------------------------------------------------------------
// PASS 1: streaming epilogue, 8 cols per thread: BN + softplus*sigmoid +
// 2x red.v4 scatter to out[dst].
// ---------------------------------------------------------------------------
__global__ __launch_bounds__(256)
void pass1_kernel(const void* __restrict__ eidx,
                  float* __restrict__ out) {
    __shared__ float sBN[2 * NOUT];
    const int tid = threadIdx.x;
    if (tid < NOUT) sBN[tid] = g_scale[tid];
    else            sBN[128 + (tid - 128)] = g_shift[tid - 128];
    __syncthreads();

    long long i = (long long)blockIdx.x * 256 + tid;   // NE*8 total
    int e = (int)(i >> 3), q = (int)(i & 7);           // q: 8-col octet

    int dst;
    if (g_idx64) dst = (int)reinterpret_cast<const long long*>(eidx)[2ll * e + 1];
    else         dst = reinterpret_cast<const int*>(eidx)[2 * e + 1];

    const __half* row = g_pre_h + (size_t)e * NOUT;
    __half2 hc[4], hf[4];
    *reinterpret_cast<uint4*>(hc) = *reinterpret_cast<const uint4*>(row + q * 8);
    *reinterpret_cast<uint4*>(hf) = *reinterpret_cast<const uint4*>(row + 64 + q * 8);

    float m[8];
#pragma unroll
    for (int u = 0; u < 4; u++) {
        float2 c2 = __half22float2(hc[u]);
        float2 f2 = __half22float2(hf[u]);
        int c = q * 8 + u * 2;
        float vc0 = c2.x * sBN[c]          + sBN[NOUT + c];
        float vc1 = c2.y * sBN[c + 1]      + sBN[NOUT + c + 1];
        float vf0 = f2.x * sBN[64 + c]     + sBN[NOUT + 64 + c];
        float vf1 = f2.y * sBN[64 + c + 1] + sBN[NOUT + 64 + c + 1];
        float sp0 = fmaxf(vc0, 0.f) + __logf(1.f + __expf(-fabsf(vc0)));
        float sp1 = fmaxf(vc1, 0.f) + __logf(1.f + __expf(-fabsf(vc1)));
        float sg0 = __fdividef(1.f, 1.f + __expf(-vf0));
        float sg1 = __fdividef(1.f, 1.f + __expf(-vf1));
        m[u * 2]     = sp0 * sg0;
        m[u * 2 + 1] = sp1 * sg1;
    }
    float* ptr = out + (long long)dst * ND + q * 8;
    asm volatile("red.global.add.v4.f32 [%0], {%1,%2,%3,%4};"
                 :: "l"(ptr), "f"(m[0]), "f"(m[1]), "f"(m[2]), "f"(m[3])
                 : "memory");
    asm volatile("red.global.add.v4.f32 [%0], {%1,%2,%3,%4};"
                 :: "l"(ptr + 4), "f"(m[4]), "f"(m[5]), "f"(m[6]), "f"(m[7])
                 : "memory");
}

// ---------------------------------------------------------------------------
extern "C" void kernel_launch(void* const* d_in, const int* in_sizes, int n_in,
                              void* d_out, int out_size) {
    const float* atom  = (const float*)d_in[0];
    const float* edgef = (const float*)d_in[1];
    const float* Wf    = (const float*)d_in[2];
    const float* gf    = (const float*)d_in[4];
    const float* bf    = (const float*)d_in[5];
    const float* Wc    = (const float*)d_in[6];
    const float* gc    = (const float*)d_in[8];
    const float* bc    = (const float*)d_in[9];
    const void*  eidx  = d_in[10];
    float* out = (float*)d_out;

    cudaFuncSetAttribute(pass0_kernel,
                         cudaFuncAttributeMaxDynamicSharedMemorySize,
                         SMEM0_BYTES);

    prep_kernel<<<2048, 256>>>(atom, Wf, Wc, (const int*)eidx, out);
    pass0_kernel<<<GRID0, THREADS0, SMEM0_BYTES>>>(edgef, eidx);
    finalize_kernel<<<1, 128>>>(gc, bc, gf, bf);
    pass1_kernel<<<(NE * 8) / 256, 256>>>(eidx, out);
}

// round 16
// speedup vs baseline: 1.5840x; 1.0394x over previous
#include <cuda_runtime.h>
#include <cuda_fp16.h>
#include <mma.h>
#include <math.h>
#include <stdint.h>

using namespace nvcuda;

#define NA 50000
#define NE 800000
#define ND 64
#define FULL 192
#define NOUT 128          // cols 0..63 = core, 64..127 = filter
#define ET 128            // edges per tile
#define NTILES (NE / ET)  // 6250
#define GRID0 296         // 2 persistent CTAs per SM
#define THREADS0 256
#define WLDH 136          // W smem leading dim (halves)
#define ZLDH 72           // z chunk leading dim (halves): 64 + 8 pad
#define BN_EPS 1e-5f

// dyn smem: W (192x136 h) + 3 z-chunks (128x72 h) + idx[2][2][128] + stats
#define SMEM0_BYTES ((FULL * WLDH + 3 * ET * ZLDH) * 2 + 4 * ET * 4 + 2 * NOUT * 4)

__device__ __align__(16) __half g_Wt_h[FULL * NOUT];   // Wt[k][o] half
__device__ __align__(16) __half g_atom_h[NA * ND];
__device__ float g_sum[NOUT];
__device__ float g_sumsq[NOUT];
__device__ float g_scale[NOUT];
__device__ float g_shift[NOUT];
__device__ int   g_idx64;
__device__ __align__(16) __half g_pre_h[(size_t)NE * NOUT];  // 204.8 MB scratch

__device__ __forceinline__ void cp_async16(void* sdst, const void* gsrc) {
    unsigned saddr = (unsigned)__cvta_generic_to_shared(sdst);
    asm volatile("cp.async.ca.shared.global [%0], [%1], 16;"
                 :: "r"(saddr), "l"(gsrc) : "memory");
}

// ---------------------------------------------------------------------------
// prep: out = atom copy; atom/W -> half; zero stats; idx dtype sniff.
// (edge features are read as f32 directly by pass0 — no pre-conversion)
// ---------------------------------------------------------------------------
__global__ void prep_kernel(const float* __restrict__ atom,
                            const float* __restrict__ Wf,
                            const float* __restrict__ Wc,
                            const int* __restrict__ eidx_i32,
                            float* __restrict__ out) {
    int tid = blockIdx.x * blockDim.x + threadIdx.x;
    int stride = gridDim.x * blockDim.x;

    for (int i = tid; i < (NA * ND) / 4; i += stride) {
        float4 v = reinterpret_cast<const float4*>(atom)[i];
        reinterpret_cast<float4*>(out)[i] = v;
        __half2* h = reinterpret_cast<__half2*>(g_atom_h) + 2 * i;
        h[0] = __floats2half2_rn(v.x, v.y);
        h[1] = __floats2half2_rn(v.z, v.w);
    }
    for (int i = tid; i < FULL * NOUT; i += stride) {
        int k = i / NOUT, o = i % NOUT;
        float w = (o < ND) ? Wc[o * FULL + k] : Wf[(o - ND) * FULL + k];
        g_Wt_h[i] = __float2half_rn(w);   // bias cancels inside batchnorm
    }
    if (tid < NOUT) { g_sum[tid] = 0.f; g_sumsq[tid] = 0.f; }
    if (tid == 0) {
        int any = 0;
        for (int k = 0; k < 512; k++) any |= eidx_i32[2 * k + 1];
        g_idx64 = (any == 0) ? 1 : 0;   // int64 => zero high words
    }
}

// ---------------------------------------------------------------------------
__global__ void finalize_kernel(const float* __restrict__ gc,
                                const float* __restrict__ bc,
                                const float* __restrict__ gf,
                                const float* __restrict__ bf) {
    int c = threadIdx.x;
    if (c < NOUT) {
        float mean = g_sum[c] * (1.f / (float)NE);
        float var  = g_sumsq[c] * (1.f / (float)NE) - mean * mean;
        float inv  = rsqrtf(var + BN_EPS);
        float gamma = (c < ND) ? gc[c] : gf[c - ND];
        float beta  = (c < ND) ? bc[c] : bf[c - ND];
        g_scale[c] = inv * gamma;
        g_shift[c] = beta - mean * inv * gamma;
    }
}

// ---------------------------------------------------------------------------
// PASS 0: persistent fp16 GEMM, 296 blocks x 256 threads (2 CTAs/SM).
// W resident in smem. 128-edge tiles, K in 3 chunks of 64 halves (dst/src
// via cp.async of pre-converted halves; edge via batched f32 LDG (MLP=8) +
// cvt + STS), triple-buffered: one barrier per chunk, none in the epilogue.
// Warp = 64 edges (4 m frags) x 32 cols (2 n frags). Pre-activations packed
// to half2 and stored straight from accumulator registers; column stats
// from registers (HMMA.16816 layout) via shfl + smem atomics.
// ---------------------------------------------------------------------------
__global__ __launch_bounds__(THREADS0, 2)
void pass0_kernel(const float* __restrict__ edgef,
                  const void*  __restrict__ eidx) {
    extern __shared__ __align__(16) unsigned char smraw[];
    __half* sW = reinterpret_cast<__half*>(smraw);        // 192*136 halves
    __half* zb[3];
    zb[0] = sW + FULL * WLDH;                             // 128*72 halves each
    zb[1] = zb[0] + ET * ZLDH;
    zb[2] = zb[1] + ET * ZLDH;
    int* sSrc = reinterpret_cast<int*>(zb[2] + ET * ZLDH);   // [2][ET]
    int* sDst = sSrc + 2 * ET;
    float* sSum = reinterpret_cast<float*>(sDst + 2 * ET);   // [NOUT]
    float* sSq  = sSum + NOUT;

    const int tid  = threadIdx.x;
    const int lane = tid & 31;
    const int bid  = blockIdx.x;
    const int nt   = (NTILES - bid + GRID0 - 1) / GRID0;  // tiles bid + t*296
    const bool i64 = (g_idx64 != 0);

    auto stageIdx = [&](int t) {
        if (tid < ET && t < nt) {
            int slot = t & 1;
            long long e = ((long long)bid + (long long)t * GRID0) * ET + tid;
            if (i64) {
                const long long* p = reinterpret_cast<const long long*>(eidx);
                sSrc[slot * ET + tid] = (int)p[2 * e];
                sDst[slot * ET + tid] = (int)p[2 * e + 1];
            } else {
                const int* p = reinterpret_cast<const int*>(eidx);
                sSrc[slot * ET + tid] = p[2 * e];
                sDst[slot * ET + tid] = p[2 * e + 1];
            }
        }
    };
    // gather K-chunk c (tile t = c/3, phase p = c%3) into zb[c%3].
    // p<2: cp.async of pre-converted halves. p==2: batched f32 LDGs
    // (8 x LDG.128 in flight) then cvt + STS. Always commits a group.
    auto gather = [&](int c) {
        int t = c / 3, p = c - 3 * t;
        if (t < nt) {
            int islot = t & 1;
            long long e0 = ((long long)bid + (long long)t * GRID0) * ET;
            __half* zbuf = zb[c % 3];
            if (p < 2) {
                for (int i = tid; i < ET * 8; i += THREADS0) {
                    int e = i >> 3, q = i & 7;
                    const __half* g = (p == 0)
                        ? g_atom_h + (long long)sDst[islot*ET + e] * ND + q * 8
                        : g_atom_h + (long long)sSrc[islot*ET + e] * ND + q * 8;
                    cp_async16(zbuf + e * ZLDH + q * 8, g);
                }
            } else {
                // ET*8 = 1024 tasks / 256 threads = exactly 4 per thread
                float4 v[8];
#pragma unroll
                for (int j = 0; j < 4; j++) {
                    int i = tid + j * THREADS0;
                    int e = i >> 3, q = i & 7;
                    const float4* gp = reinterpret_cast<const float4*>(
                        edgef + (e0 + e) * ND + q * 8);
                    v[2*j]   = gp[0];
                    v[2*j+1] = gp[1];
                }
#pragma unroll
                for (int j = 0; j < 4; j++) {
                    int i = tid + j * THREADS0;
                    int e = i >> 3, q = i & 7;
                    __half2 h[4];
                    h[0] = __floats2half2_rn(v[2*j].x,   v[2*j].y);
                    h[1] = __floats2half2_rn(v[2*j].z,   v[2*j].w);
                    h[2] = __floats2half2_rn(v[2*j+1].x, v[2*j+1].y);
                    h[3] = __floats2half2_rn(v[2*j+1].z, v[2*j+1].w);
                    *reinterpret_cast<uint4*>(zbuf + e * ZLDH + q * 8)
                        = *reinterpret_cast<uint4*>(h);
                }
            }
        }
        asm volatile("cp.async.commit_group;" ::: "memory");
    };

    // ---- prologue: idx0 + stats zero; W copy + chunk0 (grp 0); chunk1 (grp 1)
    stageIdx(0);
    if (tid < NOUT) { sSum[tid] = 0.f; sSq[tid] = 0.f; }
    __syncthreads();
    for (int i = tid; i < FULL * 16; i += THREADS0) {
        int k = i >> 4, q = i & 15;
        cp_async16(sW + k * WLDH + q * 8, g_Wt_h + k * NOUT + q * 8);
    }
    gather(0);          // W + chunk0 committed together
    gather(1);

    const int w  = tid >> 5;
    const int m0 = (w & 1) * 64;       // 4 m-fragments (64 edges)
    const int n0 = (w >> 1) * 32;      // 2 n-fragments (32 cols)
    const int g  = lane >> 2;          // acc row within 8
    const int cc = (lane & 3) * 2;     // acc col pair base

    wmma::fragment<wmma::matrix_a, 16, 16, 16, __half, wmma::row_major> a[4];
    wmma::fragment<wmma::matrix_b, 16, 16, 16, __half, wmma::row_major> b0, b1;
    wmma::fragment<wmma::accumulator, 16, 16, 16, float> acc[4][2];

    for (int t = 0; t < nt; t++) {
        long long e0 = ((long long)bid + (long long)t * GRID0) * ET;

#pragma unroll
        for (int p = 0; p < 3; p++) {
            const int c = 3 * t + p;
            asm volatile("cp.async.wait_group 1;" ::: "memory");
            __syncthreads();             // chunk c visible; zb[(c+2)%3] free

            if (p == 0) {
                stageIdx(t + 1);         // slot (t+1)&1; barrier at c+1 covers
#pragma unroll
                for (int m = 0; m < 4; m++)
#pragma unroll
                    for (int n = 0; n < 2; n++) wmma::fill_fragment(acc[m][n], 0.f);
            }

            const __half* z = zb[c % 3];
#pragma unroll
            for (int k = 0; k < 4; k++) {
#pragma unroll
                for (int m = 0; m < 4; m++)
                    wmma::load_matrix_sync(a[m], z + (m0 + m * 16) * ZLDH + k * 16, ZLDH);
                wmma::load_matrix_sync(b0, sW + (p * 64 + k * 16) * WLDH + n0,      WLDH);
                wmma::load_matrix_sync(b1, sW + (p * 64 + k * 16) * WLDH + n0 + 16, WLDH);
#pragma unroll
                for (int m = 0; m < 4; m++) {
                    wmma::mma_sync(acc[m][0], a[m], b0, acc[m][0]);
                    wmma::mma_sync(acc[m][1], a[m], b1, acc[m][1]);
                }
            }
            gather(c + 2);               // writes zb[(c+2)%3], freed above
        }

        // ---- tile epilogue (no barrier): acc regs -> half2 -> g_pre_h.
        // HMMA.16816 acc layout: x[0,1]=(g,cc),(g,cc+1); x[2,3]=rows+8;
        // x[4..7]=cols+8; g=lane>>2, cc=(lane&3)*2.
#pragma unroll
        for (int m = 0; m < 4; m++) {
            size_t rb = (size_t)(e0 + m0 + m * 16);
#pragma unroll
            for (int n = 0; n < 2; n++) {
                const float* x = acc[m][n].x;
                int col = n0 + n * 16 + cc;
                *reinterpret_cast<__half2*>(g_pre_h + (rb + g) * NOUT + col)
                    = __floats2half2_rn(x[0], x[1]);
                *reinterpret_cast<__half2*>(g_pre_h + (rb + g + 8) * NOUT + col)
                    = __floats2half2_rn(x[2], x[3]);
                *reinterpret_cast<__half2*>(g_pre_h + (rb + g) * NOUT + col + 8)
                    = __floats2half2_rn(x[4], x[5]);
                *reinterpret_cast<__half2*>(g_pre_h + (rb + g + 8) * NOUT + col + 8)
                    = __floats2half2_rn(x[6], x[7]);
            }
        }

        // ---- stats from f32 registers (shfl reduce + smem atomics) ----
#pragma unroll
        for (int n = 0; n < 2; n++) {
            float ps[4] = {0.f, 0.f, 0.f, 0.f};
            float qs[4] = {0.f, 0.f, 0.f, 0.f};
#pragma unroll
            for (int m = 0; m < 4; m++) {
                const float* x = acc[m][n].x;
                ps[0] += x[0] + x[2];  qs[0] += x[0]*x[0] + x[2]*x[2];
                ps[1] += x[1] + x[3];  qs[1] += x[1]*x[1] + x[3]*x[3];
                ps[2] += x[4] + x[6];  qs[2] += x[4]*x[4] + x[6]*x[6];
                ps[3] += x[5] + x[7];  qs[3] += x[5]*x[5] + x[7]*x[7];
            }
#pragma unroll
            for (int d = 4; d < 32; d <<= 1) {
#pragma unroll
                for (int u = 0; u < 4; u++) {
                    ps[u] += __shfl_xor_sync(0xFFFFFFFFu, ps[u], d);
                    qs[u] += __shfl_xor_sync(0xFFFFFFFFu, qs[u], d);
                }
            }
            if (lane < 4) {
                int cb = n0 + n * 16 + lane * 2;
                atomicAdd(&sSum[cb],     ps[0]);  atomicAdd(&sSq[cb],     qs[0]);
                atomicAdd(&sSum[cb + 1], ps[1]);  atomicAdd(&sSq[cb + 1], qs[1]);
                atomicAdd(&sSum[cb + 8], ps[2]);  atomicAdd(&sSq[cb + 8], qs[2]);
                atomicAdd(&sSum[cb + 9], ps[3]);  atomicAdd(&sSq[cb + 9], qs[3]);
            }
        }
    }

    __syncthreads();
    if (tid < NOUT) {
        atomicAdd(&g_sum[tid],   sSum[tid]);
        atomicAdd(&g_sumsq[tid], sSq[tid]);
    }
}

// ---------------------------------------------------------------------------
// PASS 1: streaming epilogue over half pre-acts, 4 cols per thread:
// BN + softplus*sigmoid + red.v4 scatter to out[dst].
// ---------------------------------------------------------------------------
__global__ __launch_bounds__(256)
void pass1_kernel(const void* __restrict__ eidx,
                  float* __restrict__ out) {
    __shared__ float sBN[2 * NOUT];
    const int tid = threadIdx.x;
    if (tid < NOUT) sBN[tid] = g_scale[tid];
    else            sBN[128 + (tid - 128)] = g_shift[tid - 128];
    __syncthreads();

    long long i = (long long)blockIdx.x * 256 + tid;   // NE*16 total
    int e = (int)(i >> 4), q = (int)(i & 15);

    int dst;
    if (g_idx64) dst = (int)reinterpret_cast<const long long*>(eidx)[2ll * e + 1];
    else         dst = reinterpret_cast<const int*>(eidx)[2 * e + 1];

    const __half* row = g_pre_h + (size_t)e * NOUT;
    __half2 hc[2], hf[2];
    *reinterpret_cast<uint2*>(hc) = *reinterpret_cast<const uint2*>(row + q * 4);
    *reinterpret_cast<uint2*>(hf) = *reinterpret_cast<const uint2*>(row + 64 + q * 4);
    float2 c01 = __half22float2(hc[0]), c23 = __half22float2(hc[1]);
    float2 f01 = __half22float2(hf[0]), f23 = __half22float2(hf[1]);
    float xc[4] = {c01.x, c01.y, c23.x, c23.y};
    float xf[4] = {f01.x, f01.y, f23.x, f23.y};

    float m[4];
#pragma unroll
    for (int u = 0; u < 4; u++) {
        int c = q * 4 + u;
        float vc = xc[u] * sBN[c]      + sBN[NOUT + c];
        float vf = xf[u] * sBN[64 + c] + sBN[NOUT + 64 + c];
        // softplus via MUFU: max(x,0) + log(1 + exp(-|x|))
        float sp = fmaxf(vc, 0.f) + __logf(1.f + __expf(-fabsf(vc)));
        float sg = __fdividef(1.f, 1.f + __expf(-vf));            // sigmoid
        m[u] = sp * sg;
    }
    float* ptr = out + (long long)dst * ND + q * 4;
    asm volatile("red.global.add.v4.f32 [%0], {%1,%2,%3,%4};"
                 :: "l"(ptr), "f"(m[0]), "f"(m[1]), "f"(m[2]), "f"(m[3])
                 : "memory");
}

// ---------------------------------------------------------------------------
extern "C" void kernel_launch(void* const* d_in, const int* in_sizes, int n_in,
                              void* d_out, int out_size) {
    const float* atom  = (const float*)d_in[0];
    const float* edgef = (const float*)d_in[1];
    const float* Wf    = (const float*)d_in[2];
    const float* gf    = (const float*)d_in[4];
    const float* bf    = (const float*)d_in[5];
    const float* Wc    = (const float*)d_in[6];
    const float* gc    = (const float*)d_in[8];
    const float* bc    = (const float*)d_in[9];
    const void*  eidx  = d_in[10];
    float* out = (float*)d_out;

    cudaFuncSetAttribute(pass0_kernel,
                         cudaFuncAttributeMaxDynamicSharedMemorySize,
                         SMEM0_BYTES);

    prep_kernel<<<2048, 256>>>(atom, Wf, Wc, (const int*)eidx, out);
    pass0_kernel<<<GRID0, THREADS0, SMEM0_BYTES>>>(edgef, eidx);
    finalize_kernel<<<1, 128>>>(gc, bc, gf, bf);
    pass1_kernel<<<(NE * 16) / 256, 256>>>(eidx, out);
}

// round 17
// speedup vs baseline: 1.6224x; 1.0242x over previous
#include <cuda_runtime.h>
#include <cuda_fp16.h>
#include <mma.h>
#include <math.h>
#include <stdint.h>

using namespace nvcuda;

#define NA 50000
#define NE 800000
#define ND 64
#define FULL 192
#define NOUT 128          // cols 0..63 = core, 64..127 = filter
#define ET 128            // edges per tile
#define NTILES (NE / ET)  // 6250
#define GRID0 296         // 2 persistent CTAs per SM
#define THREADS0 256
#define WLDH 136          // W smem leading dim (halves)
#define ZLDH 72           // z chunk leading dim (halves): 64 + 8 pad
#define BN_EPS 1e-5f

// dyn smem: W (192x136 h) + 3 z-chunks (128x72 h) + idx[2][2][128] + stats
#define SMEM0_BYTES ((FULL * WLDH + 3 * ET * ZLDH) * 2 + 4 * ET * 4 + 2 * NOUT * 4)

__device__ __align__(16) __half g_Wt_h[FULL * NOUT];   // Wt[k][o] half
__device__ __align__(16) __half g_atom_h[NA * ND];
__device__ float g_sum[NOUT];
__device__ float g_sumsq[NOUT];
__device__ float g_scale[NOUT];
__device__ float g_shift[NOUT];
__device__ int   g_idx64;
__device__ __align__(16) __half g_pre_h[(size_t)NE * NOUT];  // 204.8 MB scratch

__device__ __forceinline__ void cp_async16(void* sdst, const void* gsrc) {
    unsigned saddr = (unsigned)__cvta_generic_to_shared(sdst);
    asm volatile("cp.async.ca.shared.global [%0], [%1], 16;"
                 :: "r"(saddr), "l"(gsrc) : "memory");
}
// L2-only variant for random gathers (keeps L1 for LDSM working set)
__device__ __forceinline__ void cp_async16_cg(void* sdst, const void* gsrc) {
    unsigned saddr = (unsigned)__cvta_generic_to_shared(sdst);
    asm volatile("cp.async.cg.shared.global [%0], [%1], 16;"
                 :: "r"(saddr), "l"(gsrc) : "memory");
}
__device__ __forceinline__ float fast_tanh(float x) {
    float y;
    asm("tanh.approx.f32 %0, %1;" : "=f"(y) : "f"(x));
    return y;
}

// ---------------------------------------------------------------------------
// prep: out = atom copy; atom/W -> half; zero stats; idx dtype sniff.
// (edge features are read as f32 directly by pass0 — no pre-conversion)
// ---------------------------------------------------------------------------
__global__ void prep_kernel(const float* __restrict__ atom,
                            const float* __restrict__ Wf,
                            const float* __restrict__ Wc,
                            const int* __restrict__ eidx_i32,
                            float* __restrict__ out) {
    int tid = blockIdx.x * blockDim.x + threadIdx.x;
    int stride = gridDim.x * blockDim.x;

    for (int i = tid; i < (NA * ND) / 4; i += stride) {
        float4 v = reinterpret_cast<const float4*>(atom)[i];
        reinterpret_cast<float4*>(out)[i] = v;
        __half2* h = reinterpret_cast<__half2*>(g_atom_h) + 2 * i;
        h[0] = __floats2half2_rn(v.x, v.y);
        h[1] = __floats2half2_rn(v.z, v.w);
    }
    for (int i = tid; i < FULL * NOUT; i += stride) {
        int k = i / NOUT, o = i % NOUT;
        float w = (o < ND) ? Wc[o * FULL + k] : Wf[(o - ND) * FULL + k];
        g_Wt_h[i] = __float2half_rn(w);   // bias cancels inside batchnorm
    }
    if (tid < NOUT) { g_sum[tid] = 0.f; g_sumsq[tid] = 0.f; }
    if (tid == 0) {
        int any = 0;
        for (int k = 0; k < 512; k++) any |= eidx_i32[2 * k + 1];
        g_idx64 = (any == 0) ? 1 : 0;   // int64 => zero high words
    }
}

// ---------------------------------------------------------------------------
__global__ void finalize_kernel(const float* __restrict__ gc,
                                const float* __restrict__ bc,
                                const float* __restrict__ gf,
                                const float* __restrict__ bf) {
    int c = threadIdx.x;
    if (c < NOUT) {
        float mean = g_sum[c] * (1.f / (float)NE);
        float var  = g_sumsq[c] * (1.f / (float)NE) - mean * mean;
        float inv  = rsqrtf(var + BN_EPS);
        float gamma = (c < ND) ? gc[c] : gf[c - ND];
        float beta  = (c < ND) ? bc[c] : bf[c - ND];
        g_scale[c] = inv * gamma;
        g_shift[c] = beta - mean * inv * gamma;
    }
}

// ---------------------------------------------------------------------------
// PASS 0: persistent fp16 GEMM, 296 blocks x 256 threads (2 CTAs/SM).
// W resident in smem. 128-edge tiles, K in 3 chunks of 64 halves (dst/src
// via cp.async.cg of pre-converted halves; edge via batched f32 LDG (MLP=8)
// + cvt + STS), triple-buffered: one barrier per chunk, none in the
// epilogue. Warp = 64 edges (4 m frags) x 32 cols (2 n frags). Pre-
// activations packed to half2 straight from accumulator registers; column
// stats from registers (HMMA.16816 layout) via shfl + smem atomics.
// ---------------------------------------------------------------------------
__global__ __launch_bounds__(THREADS0, 2)
void pass0_kernel(const float* __restrict__ edgef,
                  const void*  __restrict__ eidx) {
    extern __shared__ __align__(16) unsigned char smraw[];
    __half* sW = reinterpret_cast<__half*>(smraw);        // 192*136 halves
    __half* zb[3];
    zb[0] = sW + FULL * WLDH;                             // 128*72 halves each
    zb[1] = zb[0] + ET * ZLDH;
    zb[2] = zb[1] + ET * ZLDH;
    int* sSrc = reinterpret_cast<int*>(zb[2] + ET * ZLDH);   // [2][ET]
    int* sDst = sSrc + 2 * ET;
    float* sSum = reinterpret_cast<float*>(sDst + 2 * ET);   // [NOUT]
    float* sSq  = sSum + NOUT;

    const int tid  = threadIdx.x;
    const int lane = tid & 31;
    const int bid  = blockIdx.x;
    const int nt   = (NTILES - bid + GRID0 - 1) / GRID0;  // tiles bid + t*296
    const bool i64 = (g_idx64 != 0);

    auto stageIdx = [&](int t) {
        if (tid < ET && t < nt) {
            int slot = t & 1;
            long long e = ((long long)bid + (long long)t * GRID0) * ET + tid;
            if (i64) {
                const long long* p = reinterpret_cast<const long long*>(eidx);
                sSrc[slot * ET + tid] = (int)p[2 * e];
                sDst[slot * ET + tid] = (int)p[2 * e + 1];
            } else {
                const int* p = reinterpret_cast<const int*>(eidx);
                sSrc[slot * ET + tid] = p[2 * e];
                sDst[slot * ET + tid] = p[2 * e + 1];
            }
        }
    };
    // gather K-chunk c (tile t = c/3, phase p = c%3) into zb[c%3].
    // p<2: cp.async.cg of pre-converted halves. p==2: batched f32 LDGs
    // (8 x LDG.128 in flight) then cvt + STS. Always commits a group.
    auto gather = [&](int c) {
        int t = c / 3, p = c - 3 * t;
        if (t < nt) {
            int islot = t & 1;
            long long e0 = ((long long)bid + (long long)t * GRID0) * ET;
            __half* zbuf = zb[c % 3];
            if (p < 2) {
                for (int i = tid; i < ET * 8; i += THREADS0) {
                    int e = i >> 3, q = i & 7;
                    const __half* g = (p == 0)
                        ? g_atom_h + (long long)sDst[islot*ET + e] * ND + q * 8
                        : g_atom_h + (long long)sSrc[islot*ET + e] * ND + q * 8;
                    cp_async16_cg(zbuf + e * ZLDH + q * 8, g);
                }
            } else {
                // ET*8 = 1024 tasks / 256 threads = exactly 4 per thread
                float4 v[8];
#pragma unroll
                for (int j = 0; j < 4; j++) {
                    int i = tid + j * THREADS0;
                    int e = i >> 3, q = i & 7;
                    const float4* gp = reinterpret_cast<const float4*>(
                        edgef + (e0 + e) * ND + q * 8);
                    v[2*j]   = gp[0];
                    v[2*j+1] = gp[1];
                }
#pragma unroll
                for (int j = 0; j < 4; j++) {
                    int i = tid + j * THREADS0;
                    int e = i >> 3, q = i & 7;
                    __half2 h[4];
                    h[0] = __floats2half2_rn(v[2*j].x,   v[2*j].y);
                    h[1] = __floats2half2_rn(v[2*j].z,   v[2*j].w);
                    h[2] = __floats2half2_rn(v[2*j+1].x, v[2*j+1].y);
                    h[3] = __floats2half2_rn(v[2*j+1].z, v[2*j+1].w);
                    *reinterpret_cast<uint4*>(zbuf + e * ZLDH + q * 8)
                        = *reinterpret_cast<uint4*>(h);
                }
            }
        }
        asm volatile("cp.async.commit_group;" ::: "memory");
    };

    // ---- prologue: idx0 + stats zero; W copy + chunk0 (grp 0); chunk1 (grp 1)
    stageIdx(0);
    if (tid < NOUT) { sSum[tid] = 0.f; sSq[tid] = 0.f; }
    __syncthreads();
    for (int i = tid; i < FULL * 16; i += THREADS0) {
        int k = i >> 4, q = i & 15;
        cp_async16(sW + k * WLDH + q * 8, g_Wt_h + k * NOUT + q * 8);
    }
    gather(0);          // W + chunk0 committed together
    gather(1);

    const int w  = tid >> 5;
    const int m0 = (w & 1) * 64;       // 4 m-fragments (64 edges)
    const int n0 = (w >> 1) * 32;      // 2 n-fragments (32 cols)
    const int g  = lane >> 2;          // acc row within 8
    const int cc = (lane & 3) * 2;     // acc col pair base

    wmma::fragment<wmma::matrix_a, 16, 16, 16, __half, wmma::row_major> a[4];
    wmma::fragment<wmma::matrix_b, 16, 16, 16, __half, wmma::row_major> b0, b1;
    wmma::fragment<wmma::accumulator, 16, 16, 16, float> acc[4][2];

    for (int t = 0; t < nt; t++) {
        long long e0 = ((long long)bid + (long long)t * GRID0) * ET;

#pragma unroll
        for (int p = 0; p < 3; p++) {
            const int c = 3 * t + p;
            asm volatile("cp.async.wait_group 1;" ::: "memory");
            __syncthreads();             // chunk c visible; zb[(c+2)%3] free

            if (p == 0) {
                stageIdx(t + 1);         // slot (t+1)&1; barrier at c+1 covers
#pragma unroll
                for (int m = 0; m < 4; m++)
#pragma unroll
                    for (int n = 0; n < 2; n++) wmma::fill_fragment(acc[m][n], 0.f);
            }

            const __half* z = zb[c % 3];
#pragma unroll
            for (int k = 0; k < 4; k++) {
#pragma unroll
                for (int m = 0; m < 4; m++)
                    wmma::load_matrix_sync(a[m], z + (m0 + m * 16) * ZLDH + k * 16, ZLDH);
                wmma::load_matrix_sync(b0, sW + (p * 64 + k * 16) * WLDH + n0,      WLDH);
                wmma::load_matrix_sync(b1, sW + (p * 64 + k * 16) * WLDH + n0 + 16, WLDH);
#pragma unroll
                for (int m = 0; m < 4; m++) {
                    wmma::mma_sync(acc[m][0], a[m], b0, acc[m][0]);
                    wmma::mma_sync(acc[m][1], a[m], b1, acc[m][1]);
                }
            }
            gather(c + 2);               // writes zb[(c+2)%3], freed above
        }

        // ---- tile epilogue (no barrier): acc regs -> half2 -> g_pre_h.
        // HMMA.16816 acc layout: x[0,1]=(g,cc),(g,cc+1); x[2,3]=rows+8;
        // x[4..7]=cols+8; g=lane>>2, cc=(lane&3)*2.
#pragma unroll
        for (int m = 0; m < 4; m++) {
            size_t rb = (size_t)(e0 + m0 + m * 16);
#pragma unroll
            for (int n = 0; n < 2; n++) {
                const float* x = acc[m][n].x;
                int col = n0 + n * 16 + cc;
                *reinterpret_cast<__half2*>(g_pre_h + (rb + g) * NOUT + col)
                    = __floats2half2_rn(x[0], x[1]);
                *reinterpret_cast<__half2*>(g_pre_h + (rb + g + 8) * NOUT + col)
                    = __floats2half2_rn(x[2], x[3]);
                *reinterpret_cast<__half2*>(g_pre_h + (rb + g) * NOUT + col + 8)
                    = __floats2half2_rn(x[4], x[5]);
                *reinterpret_cast<__half2*>(g_pre_h + (rb + g + 8) * NOUT + col + 8)
                    = __floats2half2_rn(x[6], x[7]);
            }
        }

        // ---- stats from f32 registers (shfl reduce + smem atomics) ----
#pragma unroll
        for (int n = 0; n < 2; n++) {
            float ps[4] = {0.f, 0.f, 0.f, 0.f};
            float qs[4] = {0.f, 0.f, 0.f, 0.f};
#pragma unroll
            for (int m = 0; m < 4; m++) {
                const float* x = acc[m][n].x;
                ps[0] += x[0] + x[2];  qs[0] += x[0]*x[0] + x[2]*x[2];
                ps[1] += x[1] + x[3];  qs[1] += x[1]*x[1] + x[3]*x[3];
                ps[2] += x[4] + x[6];  qs[2] += x[4]*x[4] + x[6]*x[6];
                ps[3] += x[5] + x[7];  qs[3] += x[5]*x[5] + x[7]*x[7];
            }
#pragma unroll
            for (int d = 4; d < 32; d <<= 1) {
#pragma unroll
                for (int u = 0; u < 4; u++) {
                    ps[u] += __shfl_xor_sync(0xFFFFFFFFu, ps[u], d);
                    qs[u] += __shfl_xor_sync(0xFFFFFFFFu, qs[u], d);
                }
            }
            if (lane < 4) {
                int cb = n0 + n * 16 + lane * 2;
                atomicAdd(&sSum[cb],     ps[0]);  atomicAdd(&sSq[cb],     qs[0]);
                atomicAdd(&sSum[cb + 1], ps[1]);  atomicAdd(&sSq[cb + 1], qs[1]);
                atomicAdd(&sSum[cb + 8], ps[2]);  atomicAdd(&sSq[cb + 8], qs[2]);
                atomicAdd(&sSum[cb + 9], ps[3]);  atomicAdd(&sSq[cb + 9], qs[3]);
            }
        }
    }

    __syncthreads();
    if (tid < NOUT) {
        atomicAdd(&g_sum[tid],   sSum[tid]);
        atomicAdd(&g_sumsq[tid], sSq[tid]);
    }
}

// ---------------------------------------------------------------------------
// PASS 1: streaming epilogue over half pre-acts, 4 cols per thread:
// BN + softplus * (tanh-based sigmoid) + red.v4 scatter to out[dst].
// ---------------------------------------------------------------------------
__global__ __launch_bounds__(256)
void pass1_kernel(const void* __restrict__ eidx,
                  float* __restrict__ out) {
    __shared__ float sBN[2 * NOUT];
    const int tid = threadIdx.x;
    if (tid < NOUT) sBN[tid] = g_scale[tid];
    else            sBN[128 + (tid - 128)] = g_shift[tid - 128];
    __syncthreads();

    long long i = (long long)blockIdx.x * 256 + tid;   // NE*16 total
    int e = (int)(i >> 4), q = (int)(i & 15);

    int dst;
    if (g_idx64) dst = (int)reinterpret_cast<const long long*>(eidx)[2ll * e + 1];
    else         dst = reinterpret_cast<const int*>(eidx)[2 * e + 1];

    const __half* row = g_pre_h + (size_t)e * NOUT;
    __half2 hc[2], hf[2];
    *reinterpret_cast<uint2*>(hc) = *reinterpret_cast<const uint2*>(row + q * 4);
    *reinterpret_cast<uint2*>(hf) = *reinterpret_cast<const uint2*>(row + 64 + q * 4);
    float2 c01 = __half22float2(hc[0]), c23 = __half22float2(hc[1]);
    float2 f01 = __half22float2(hf[0]), f23 = __half22float2(hf[1]);
    float xc[4] = {c01.x, c01.y, c23.x, c23.y};
    float xf[4] = {f01.x, f01.y, f23.x, f23.y};

    float m[4];
#pragma unroll
    for (int u = 0; u < 4; u++) {
        int c = q * 4 + u;
        float vc = xc[u] * sBN[c]      + sBN[NOUT + c];
        float vf = xf[u] * sBN[64 + c] + sBN[NOUT + 64 + c];
        // softplus: max(x,0) + log(1 + exp(-|x|))  (EX2 + LG2)
        float sp = fmaxf(vc, 0.f) + __logf(1.f + __expf(-fabsf(vc)));
        // sigmoid via single MUFU.TANH: 0.5*tanh(x/2) + 0.5
        float sg = fmaf(fast_tanh(vf * 0.5f), 0.5f, 0.5f);
        m[u] = sp * sg;
    }
    float* ptr = out + (long long)dst * ND + q * 4;
    asm volatile("red.global.add.v4.f32 [%0], {%1,%2,%3,%4};"
                 :: "l"(ptr), "f"(m[0]), "f"(m[1]), "f"(m[2]), "f"(m[3])
                 : "memory");
}

// ---------------------------------------------------------------------------
extern "C" void kernel_launch(void* const* d_in, const int* in_sizes, int n_in,
                              void* d_out, int out_size) {
    const float* atom  = (const float*)d_in[0];
    const float* edgef = (const float*)d_in[1];
    const float* Wf    = (const float*)d_in[2];
    const float* gf    = (const float*)d_in[4];
    const float* bf    = (const float*)d_in[5];
    const float* Wc    = (const float*)d_in[6];
    const float* gc    = (const float*)d_in[8];
    const float* bc    = (const float*)d_in[9];
    const void*  eidx  = d_in[10];
    float* out = (float*)d_out;

    cudaFuncSetAttribute(pass0_kernel,
                         cudaFuncAttributeMaxDynamicSharedMemorySize,
                         SMEM0_BYTES);

    prep_kernel<<<2048, 256>>>(atom, Wf, Wc, (const int*)eidx, out);
    pass0_kernel<<<GRID0, THREADS0, SMEM0_BYTES>>>(edgef, eidx);
    finalize_kernel<<<1, 128>>>(gc, bc, gf, bf);
    pass1_kernel<<<(NE * 16) / 256, 256>>>(eidx, out);
}